// round 11
// baseline (speedup 1.0000x reference)
#include <cuda_runtime.h>
#include <math.h>
#include <stdint.h>

#define BB   2
#define QQ   2048
#define KLEN 2048
#define KP   2049
#define DD   512
#define NH   8
#define HD   64
#define SCALE_F   0.125f
#define NEG_INF_F -1e30f
#define LN_EPS_F  1e-5f

// ---------------- tf32 mma helpers -------------------------------------------
__device__ __forceinline__ uint32_t f2tf(float f) {
    uint32_t u; asm("cvt.rna.tf32.f32 %0, %1;" : "=r"(u) : "f"(f)); return u;
}
__device__ __forceinline__ void mma8(float c[4], uint32_t a0, uint32_t a1,
                                     uint32_t a2, uint32_t a3,
                                     uint32_t b0, uint32_t b1) {
    asm volatile("mma.sync.aligned.m16n8k8.row.col.f32.tf32.tf32.f32 "
        "{%0,%1,%2,%3}, {%4,%5,%6,%7}, {%8,%9}, {%0,%1,%2,%3};"
        : "+f"(c[0]), "+f"(c[1]), "+f"(c[2]), "+f"(c[3])
        : "r"(a0), "r"(a1), "r"(a2), "r"(a3), "r"(b0), "r"(b1));
}

// fragment k-permutation within a k8 group: p = ((kk&3)<<1)|(kk>>2)
#define KPERM(kk) ((((kk) & 3) << 1) | ((kk) >> 2))
// XOR swizzle of k-group by row (rows stride multiple of 32 words)
#define SWG(kg, r) ((((kg) ^ ((r) & 3)) << 3))

// ---------------- scratch ----------------------------------------------------
__device__ float g_QN[BB * QQ * DD];
__device__ float g_KN[BB * KP * DD];
__device__ float g_VN[BB * KP * DD];
__device__ float g_QH[BB * QQ * DD];
__device__ float g_KH[BB * KP * DD];
__device__ float g_VH[BB * KP * DD];
__device__ float g_AV[BB * QQ * DD];
__device__ float g_AVO[BB * QQ * DD];
// prepped weights: tf32 bits, layout [(kt*512 + n)*32 + (kg*8 + KPERM(kk))]
__device__ float g_Pq[DD * DD];
__device__ float g_Pk[DD * DD];
__device__ float g_Pv[DD * DD];
__device__ float g_Po[DD * DD];
__device__ float g_Pg[2 * DD * DD];

// ---------------- weight prep: transpose + permute + tf32-convert -------------
__global__ void prep_w(const float* __restrict__ wq, const float* __restrict__ wk,
                       const float* __restrict__ wv, const float* __restrict__ wo,
                       const float* __restrict__ gw,
                       float* __restrict__ Pq, float* __restrict__ Pk,
                       float* __restrict__ Pv, float* __restrict__ Po,
                       float* __restrict__ Pg) {
    int z = blockIdx.z;
    const float* W = (z == 0) ? wq : (z == 1) ? wk : (z == 2) ? wv
                   : (z == 3) ? wo : gw;
    float* P       = (z == 0) ? Pq : (z == 1) ? Pk : (z == 2) ? Pv
                   : (z == 3) ? Po : Pg;
    int K = (z == 4) ? 1024 : 512;
    int kt = blockIdx.x;
    if (kt * 32 >= K) return;
    int n0 = blockIdx.y * 32;

    __shared__ float t[32][33];
    int x = threadIdx.x, y = threadIdx.y;   // block (32, 8)
    #pragma unroll
    for (int i = 0; i < 4; i++)
        t[y + 8 * i][x] = W[(size_t)(kt * 32 + y + 8 * i) * 512 + n0 + x];
    __syncthreads();

    int kg = x >> 3, p = x & 7;
    int kk = ((p & 1) << 2) | (p >> 1);     // inverse of KPERM
    int krow = kg * 8 + kk;
    #pragma unroll
    for (int i = 0; i < 4; i++) {
        int nn = y + 8 * i;
        P[((size_t)(kt * 512) + n0 + nn) * 32 + x] =
            __uint_as_float(f2tf(t[krow][nn]));
    }
}

// ---------------- merged LayerNorm (y selects q/k/v) --------------------------
__global__ void ln3_kernel(const float* __restrict__ xq,
                           const float* __restrict__ xk,
                           const float* __restrict__ xv,
                           const float* __restrict__ qg, const float* __restrict__ qb,
                           const float* __restrict__ kg, const float* __restrict__ kb,
                           const float* __restrict__ vg, const float* __restrict__ vb,
                           float* __restrict__ yq, float* __restrict__ yk,
                           float* __restrict__ yv) {
    int z = blockIdx.y;
    const float* x     = (z == 0) ? xq : (z == 1) ? xk : xv;
    const float* gamma = (z == 0) ? qg : (z == 1) ? kg : vg;
    const float* beta  = (z == 0) ? qb : (z == 1) ? kb : vb;
    float* y           = (z == 0) ? yq : (z == 1) ? yk : yv;
    int rows_in  = (z == 0) ? QQ : KLEN;
    int rows_out = (z == 0) ? QQ : KP;

    int r = blockIdx.x;
    if (r >= BB * rows_out) return;
    int b = r / rows_out;
    int j = r - b * rows_out;
    int t = threadIdx.x;

    float4 g4 = ((const float4*)gamma)[t];
    float4 b4 = ((const float4*)beta)[t];
    float4* yr = (float4*)(y + (size_t)r * DD);

    if (j >= rows_in) { yr[t] = b4; return; }

    const float4* xr = (const float4*)(x + ((size_t)b * rows_in + j) * DD);
    float4 v = xr[t];
    float s  = v.x + v.y + v.z + v.w;
    float sq = v.x*v.x + v.y*v.y + v.z*v.z + v.w*v.w;
    #pragma unroll
    for (int o = 16; o > 0; o >>= 1) {
        s  += __shfl_xor_sync(0xffffffffu, s,  o);
        sq += __shfl_xor_sync(0xffffffffu, sq, o);
    }
    __shared__ float rs[4], rq[4];
    int w = t >> 5;
    if ((t & 31) == 0) { rs[w] = s; rq[w] = sq; }
    __syncthreads();
    s  = rs[0] + rs[1] + rs[2] + rs[3];
    sq = rq[0] + rq[1] + rq[2] + rq[3];

    float mean = s * (1.0f / DD);
    float var  = sq * (1.0f / DD) - mean * mean;
    float rstd = rsqrtf(var + LN_EPS_F);

    float4 o;
    o.x = (v.x - mean) * rstd * g4.x + b4.x;
    o.y = (v.y - mean) * rstd * g4.y + b4.y;
    o.z = (v.z - mean) * rstd * g4.z + b4.z;
    o.w = (v.w - mean) * rstd * g4.w + b4.w;
    yr[t] = o;
}

// ---------------- tf32 warp-MMA GEMM body -------------------------------------
// BM=64, BN=128, BK=32; 256 thr = 8 warps (2m x 4n), warp tile 32x32.
// XOR-swizzled smem (stride 32 words): conflict-free fragment LDS.64.
#define GEMM_SMEM ((2 * 64 * 32 + 2 * 128 * 32) * 4)

extern __shared__ float smf[];

__device__ __forceinline__ void gemm_body(const float* __restrict__ A,
                                          const float* __restrict__ P,
                                          float* __restrict__ C, int M,
                                          int n0, int m0) {
    float* As0 = smf;
    float* As1 = smf + 64 * 32;
    float* Bs0 = smf + 2 * 64 * 32;
    float* Bs1 = smf + 2 * 64 * 32 + 128 * 32;
    int tid = threadIdx.x;
    int lane = tid & 31, wid = tid >> 5;
    int g = lane >> 2, t4 = lane & 3;
    int mw = wid & 1, nw = wid >> 1;

    float acc[2][4][4] = {};
    float4 ra[2], rb[4];

    auto ldg = [&](int kt) {
        int k0 = kt * 32;
        #pragma unroll
        for (int it = 0; it < 2; it++) {
            int f = tid + it * 256;            // 0..511
            int r = f >> 3; int c4 = f & 7;
            int gm = m0 + r; if (gm > M - 1) gm = M - 1;
            ra[it] = *(const float4*)(A + (size_t)gm * 512 + k0 + c4 * 4);
        }
        const float* Pb = P + ((size_t)kt * 512 + n0) * 32;
        #pragma unroll
        for (int it = 0; it < 4; it++) {
            int f = tid + it * 256;            // 0..1023
            int nr = f >> 3; int c4 = f & 7;
            rb[it] = *(const float4*)(Pb + (size_t)nr * 32 + c4 * 4);
        }
    };
    auto sts = [&](float* Ab, float* Bb) {
        #pragma unroll
        for (int it = 0; it < 2; it++) {
            int f = tid + it * 256;
            int r = f >> 3; int c4 = f & 7;
            float va[4] = {ra[it].x, ra[it].y, ra[it].z, ra[it].w};
            #pragma unroll
            for (int i = 0; i < 4; i++) {
                int k = c4 * 4 + i;
                ((uint32_t*)Ab)[r * 32 + SWG(k >> 3, r) + KPERM(k & 7)] = f2tf(va[i]);
            }
        }
        #pragma unroll
        for (int it = 0; it < 4; it++) {
            int f = tid + it * 256;
            int nr = f >> 3; int c4 = f & 7;
            *(float4*)&Bb[nr * 32 + SWG(c4 >> 1, nr) + (c4 & 1) * 4] = rb[it];
        }
    };
    auto compute = [&](float* Ab, float* Bb) {
        #pragma unroll
        for (int kg = 0; kg < 4; kg++) {
            uint2 a02[2], a13[2];
            #pragma unroll
            for (int mi = 0; mi < 2; mi++) {
                int r = mw * 32 + mi * 16 + g;
                a02[mi] = *(uint2*)((uint32_t*)Ab + r * 32 + SWG(kg, g) + 2 * t4);
                a13[mi] = *(uint2*)((uint32_t*)Ab + (r + 8) * 32 + SWG(kg, g) + 2 * t4);
            }
            #pragma unroll
            for (int ni = 0; ni < 4; ni++) {
                int nr = nw * 32 + ni * 8 + g;
                uint2 bf = *(uint2*)((uint32_t*)Bb + nr * 32 + SWG(kg, g) + 2 * t4);
                #pragma unroll
                for (int mi = 0; mi < 2; mi++)
                    mma8(acc[mi][ni], a02[mi].x, a13[mi].x, a02[mi].y, a13[mi].y,
                         bf.x, bf.y);
            }
        }
    };

    ldg(0); sts(As0, Bs0); __syncthreads();
    const int T = 16;
    for (int t = 0; t < T; t++) {
        if (t + 1 < T) ldg(t + 1);
        if (t & 1) compute(As1, Bs1); else compute(As0, Bs0);
        if (t + 1 < T) { if (t & 1) sts(As0, Bs0); else sts(As1, Bs1); }
        __syncthreads();
    }

    #pragma unroll
    for (int mi = 0; mi < 2; mi++) {
        int r0 = m0 + mw * 32 + mi * 16 + g;
        #pragma unroll
        for (int ni = 0; ni < 4; ni++) {
            int c = n0 + nw * 32 + ni * 8 + 2 * t4;
            if (r0 < M)
                *(float2*)(C + (size_t)r0 * 512 + c) =
                    make_float2(acc[mi][ni][0], acc[mi][ni][1]);
            if (r0 + 8 < M)
                *(float2*)(C + (size_t)(r0 + 8) * 512 + c) =
                    make_float2(acc[mi][ni][2], acc[mi][ni][3]);
        }
    }
}

// merged QKV projection: blockIdx.z selects which projection
__global__ void __launch_bounds__(256, 2) mm_qkv(const float* __restrict__ QN,
                                                 const float* __restrict__ KN,
                                                 const float* __restrict__ VN,
                                                 const float* __restrict__ Pq,
                                                 const float* __restrict__ Pk,
                                                 const float* __restrict__ Pv,
                                                 float* __restrict__ QH,
                                                 float* __restrict__ KH,
                                                 float* __restrict__ VH) {
    int z = blockIdx.z;
    const float* A = (z == 0) ? QN : (z == 1) ? KN : VN;
    const float* P = (z == 0) ? Pq : (z == 1) ? Pk : Pv;
    float* C       = (z == 0) ? QH : (z == 1) ? KH : VH;
    int M = (z == 0) ? BB * QQ : BB * KP;
    int m0 = blockIdx.y * 64;
    if (m0 >= M) return;
    gemm_body(A, P, C, M, blockIdx.x * 128, m0);
}

__global__ void __launch_bounds__(256, 2) mm_single(const float* __restrict__ A,
                                                    const float* __restrict__ P,
                                                    float* __restrict__ C, int M) {
    gemm_body(A, P, C, M, blockIdx.x * 128, blockIdx.y * 64);
}

// ---------------- g_net GEMM (K=1024, prepped weights) + gated residual -------
__global__ void __launch_bounds__(256, 2) mm_gnet(const float* __restrict__ Aq,
                                                  const float* __restrict__ Av,
                                                  const float* __restrict__ Pg,
                                                  const float* __restrict__ gbv,
                                                  float* __restrict__ out) {
    float* As0 = smf;
    float* As1 = smf + 64 * 32;
    float* Bs0 = smf + 2 * 64 * 32;
    float* Bs1 = smf + 2 * 64 * 32 + 128 * 32;
    int tid = threadIdx.x;
    int lane = tid & 31, wid = tid >> 5;
    int g = lane >> 2, t4 = lane & 3;
    int mw = wid & 1, nw = wid >> 1;
    int n0 = blockIdx.x * 128, m0 = blockIdx.y * 64;

    float acc[2][4][4] = {};
    float4 ra[2], rb[4];

    auto ldg = [&](int kt) {
        const float* Ap = (kt < 16) ? Aq : Av;
        int ka = (kt & 15) * 32;
        #pragma unroll
        for (int it = 0; it < 2; it++) {
            int f = tid + it * 256;
            int r = f >> 3; int c4 = f & 7;
            ra[it] = *(const float4*)(Ap + (size_t)(m0 + r) * 512 + ka + c4 * 4);
        }
        const float* Pb = Pg + ((size_t)kt * 512 + n0) * 32;
        #pragma unroll
        for (int it = 0; it < 4; it++) {
            int f = tid + it * 256;
            int nr = f >> 3; int c4 = f & 7;
            rb[it] = *(const float4*)(Pb + (size_t)nr * 32 + c4 * 4);
        }
    };
    auto sts = [&](float* Ab, float* Bb) {
        #pragma unroll
        for (int it = 0; it < 2; it++) {
            int f = tid + it * 256;
            int r = f >> 3; int c4 = f & 7;
            float va[4] = {ra[it].x, ra[it].y, ra[it].z, ra[it].w};
            #pragma unroll
            for (int i = 0; i < 4; i++) {
                int k = c4 * 4 + i;
                ((uint32_t*)Ab)[r * 32 + SWG(k >> 3, r) + KPERM(k & 7)] = f2tf(va[i]);
            }
        }
        #pragma unroll
        for (int it = 0; it < 4; it++) {
            int f = tid + it * 256;
            int nr = f >> 3; int c4 = f & 7;
            *(float4*)&Bb[nr * 32 + SWG(c4 >> 1, nr) + (c4 & 1) * 4] = rb[it];
        }
    };
    auto compute = [&](float* Ab, float* Bb) {
        #pragma unroll
        for (int kg = 0; kg < 4; kg++) {
            uint2 a02[2], a13[2];
            #pragma unroll
            for (int mi = 0; mi < 2; mi++) {
                int r = mw * 32 + mi * 16 + g;
                a02[mi] = *(uint2*)((uint32_t*)Ab + r * 32 + SWG(kg, g) + 2 * t4);
                a13[mi] = *(uint2*)((uint32_t*)Ab + (r + 8) * 32 + SWG(kg, g) + 2 * t4);
            }
            #pragma unroll
            for (int ni = 0; ni < 4; ni++) {
                int nr = nw * 32 + ni * 8 + g;
                uint2 bf = *(uint2*)((uint32_t*)Bb + nr * 32 + SWG(kg, g) + 2 * t4);
                #pragma unroll
                for (int mi = 0; mi < 2; mi++)
                    mma8(acc[mi][ni], a02[mi].x, a13[mi].x, a02[mi].y, a13[mi].y,
                         bf.x, bf.y);
            }
        }
    };

    ldg(0); sts(As0, Bs0); __syncthreads();
    const int T = 32;
    for (int t = 0; t < T; t++) {
        if (t + 1 < T) ldg(t + 1);
        if (t & 1) compute(As1, Bs1); else compute(As0, Bs0);
        if (t + 1 < T) { if (t & 1) sts(As0, Bs0); else sts(As1, Bs1); }
        __syncthreads();
    }

    #pragma unroll
    for (int mi = 0; mi < 2; mi++) {
        int r0 = m0 + mw * 32 + mi * 16 + g;
        #pragma unroll
        for (int ni = 0; ni < 4; ni++) {
            int c = n0 + nw * 32 + ni * 8 + 2 * t4;
            float2 bb = *(const float2*)(gbv + c);
            #pragma unroll
            for (int sel = 0; sel < 2; sel++) {
                size_t r = r0 + sel * 8;
                float2 qv = *(const float2*)(Aq + r * 512 + c);
                float2 av = *(const float2*)(Av + r * 512 + c);
                float s0 = acc[mi][ni][sel * 2 + 0] + bb.x;
                float s1 = acc[mi][ni][sel * 2 + 1] + bb.y;
                float g0 = 1.0f / (1.0f + __expf(-s0));
                float g1 = 1.0f / (1.0f + __expf(-s1));
                float o0 = qv.x + g0 * qv.x + (1.0f - g0) * av.x;
                float o1 = qv.y + g1 * qv.y + (1.0f - g1) * av.y;
                *(float2*)(out + r * 512 + c) = make_float2(o0, o1);
            }
        }
    }
}

// ---------------- flash attention: swizzled smem, conflict-free V staging ----
// Buffers stride 64 words: Qs[128] Ks[64] Vs[64] Ps[128] + Ms[64]
// P and V both use IDENTITY within-group key placement (consistent k ordering
// for the PV mma); Q/K use KPERM over d (consistent with each other).
#define ATT_SMEM (((128 + 64 + 64 + 128) * 64 + 64) * 4)

__global__ void __launch_bounds__(256) attn_kernel(const float* __restrict__ QHp,
                                                   const float* __restrict__ KHp,
                                                   const float* __restrict__ VHp,
                                                   const int* __restrict__ kmask,
                                                   const int* __restrict__ qmask,
                                                   float* __restrict__ AV) {
    float* Qs = smf;                 // [128][64] tf32, swizzled
    float* Ks = Qs + 128 * 64;       // [64][64]  rows=keys, cols=d (KPERM)
    float* Vs = Ks + 64 * 64;        // [64][64]  rows=d,    cols=keys (identity)
    float* Ps = Vs + 64 * 64;        // [128][64] rows=q,    cols=keys (identity)
    float* Ms = Ps + 128 * 64;       // [64]

    int tid = threadIdx.x;
    int lane = tid & 31, wid = tid >> 5;
    int g = lane >> 2, t4 = lane & 3;
    int qw = wid * 16;
    int qb = blockIdx.x * 128, h = blockIdx.y, b = blockIdx.z;
    size_t qrow0 = (size_t)b * QQ + qb;

    // stage Q (pre-scaled, tf32, swizzled, KPERM over d)
    #pragma unroll
    for (int it = 0; it < 8; it++) {
        int f = tid + it * 256; int q = f >> 4; int c4 = f & 15;
        float4 v = *(const float4*)(QHp + (qrow0 + q) * 512 + h * 64 + c4 * 4);
        float va[4] = {v.x * SCALE_F, v.y * SCALE_F, v.z * SCALE_F, v.w * SCALE_F};
        #pragma unroll
        for (int i = 0; i < 4; i++) {
            int d = c4 * 4 + i;
            ((uint32_t*)Qs)[q * 64 + SWG(d >> 3, q) + KPERM(d & 7)] = f2tf(va[i]);
        }
    }

    float mr[2] = {NEG_INF_F, NEG_INF_F};
    float lr[2] = {0.f, 0.f};
    float O[8][4] = {};

    for (int t0 = 0; t0 < KP; t0 += 64) {
        __syncthreads();
        // ---- stage K (row=key, col=d swizzled KPERM; coalesced LDG) ----
        #pragma unroll
        for (int it = 0; it < 4; it++) {
            int f = tid + it * 256; int j = f >> 4; int c4 = f & 15;
            int jg = t0 + j;
            float4 kv = make_float4(0.f, 0.f, 0.f, 0.f);
            if (jg < KP)
                kv = *(const float4*)(KHp + ((size_t)b * KP + jg) * 512 + h * 64 + c4 * 4);
            float ka[4] = {kv.x, kv.y, kv.z, kv.w};
            #pragma unroll
            for (int i = 0; i < 4; i++) {
                int d = c4 * 4 + i;
                ((uint32_t*)Ks)[j * 64 + SWG(d >> 3, j) + KPERM(d & 7)] = f2tf(ka[i]);
            }
        }
        // ---- stage V transposed (row=d, col=key IDENTITY within group) ----
        // (must match Ps identity placement: PV mma k-order consistency)
        #pragma unroll
        for (int it = 0; it < 4; it++) {
            int f = tid + it * 256; int j6 = f & 63; int dc = f >> 6;
            int jg = t0 + j6;
            float4 vv = make_float4(0.f, 0.f, 0.f, 0.f);
            if (jg < KP)
                vv = *(const float4*)(VHp + ((size_t)b * KP + jg) * 512 + h * 64 + dc * 4);
            float va[4] = {vv.x, vv.y, vv.z, vv.w};
            #pragma unroll
            for (int i = 0; i < 4; i++) {
                int d = dc * 4 + i;
                ((uint32_t*)Vs)[d * 64 + SWG(j6 >> 3, d) + (j6 & 7)] = f2tf(va[i]);
            }
        }
        if (tid < 64) {
            int jg = t0 + tid;
            bool valid = (jg < KLEN) ? (kmask[b * KLEN + jg] != 0) : (jg == KLEN);
            Ms[tid] = valid ? 0.0f : NEG_INF_F;
        }
        __syncthreads();

        // ---- S = Q K^T ----
        float s[8][4] = {};
        #pragma unroll
        for (int kg = 0; kg < 8; kg++) {
            uint2 a02 = *(uint2*)((uint32_t*)Qs + (qw + g) * 64 + SWG(kg, g) + 2 * t4);
            uint2 a13 = *(uint2*)((uint32_t*)Qs + (qw + g + 8) * 64 + SWG(kg, g) + 2 * t4);
            #pragma unroll
            for (int ni = 0; ni < 8; ni++) {
                uint2 bf = *(uint2*)((uint32_t*)Ks + (ni * 8 + g) * 64 + SWG(kg, g) + 2 * t4);
                mma8(s[ni], a02.x, a13.x, a02.y, a13.y, bf.x, bf.y);
            }
        }
        // mask
        #pragma unroll
        for (int ni = 0; ni < 8; ni++) {
            float2 mk = *(float2*)&Ms[ni * 8 + 2 * t4];
            s[ni][0] += mk.x; s[ni][1] += mk.y;
            s[ni][2] += mk.x; s[ni][3] += mk.y;
        }
        // ---- online softmax ----
        float mx0 = NEG_INF_F, mx1 = NEG_INF_F;
        #pragma unroll
        for (int ni = 0; ni < 8; ni++) {
            mx0 = fmaxf(mx0, fmaxf(s[ni][0], s[ni][1]));
            mx1 = fmaxf(mx1, fmaxf(s[ni][2], s[ni][3]));
        }
        mx0 = fmaxf(mx0, __shfl_xor_sync(0xffffffffu, mx0, 1));
        mx0 = fmaxf(mx0, __shfl_xor_sync(0xffffffffu, mx0, 2));
        mx1 = fmaxf(mx1, __shfl_xor_sync(0xffffffffu, mx1, 1));
        mx1 = fmaxf(mx1, __shfl_xor_sync(0xffffffffu, mx1, 2));
        float mn0 = fmaxf(mr[0], mx0), mn1 = fmaxf(mr[1], mx1);
        float al0 = __expf(mr[0] - mn0), al1 = __expf(mr[1] - mn1);
        float sum0 = 0.f, sum1 = 0.f;
        #pragma unroll
        for (int ni = 0; ni < 8; ni++) {
            s[ni][0] = __expf(s[ni][0] - mn0); sum0 += s[ni][0];
            s[ni][1] = __expf(s[ni][1] - mn0); sum0 += s[ni][1];
            s[ni][2] = __expf(s[ni][2] - mn1); sum1 += s[ni][2];
            s[ni][3] = __expf(s[ni][3] - mn1); sum1 += s[ni][3];
        }
        sum0 += __shfl_xor_sync(0xffffffffu, sum0, 1);
        sum0 += __shfl_xor_sync(0xffffffffu, sum0, 2);
        sum1 += __shfl_xor_sync(0xffffffffu, sum1, 1);
        sum1 += __shfl_xor_sync(0xffffffffu, sum1, 2);
        lr[0] = lr[0] * al0 + sum0;
        lr[1] = lr[1] * al1 + sum1;
        mr[0] = mn0; mr[1] = mn1;
        #pragma unroll
        for (int ni = 0; ni < 8; ni++) {
            O[ni][0] *= al0; O[ni][1] *= al0;
            O[ni][2] *= al1; O[ni][3] *= al1;
        }
        // ---- P to SMEM as STS.64 pairs: IDENTITY key placement ----
        // C fragment holds keys (ni*8 + 2t4, ni*8 + 2t4 + 1) -> positions 2t4, 2t4+1.
        #pragma unroll
        for (int ni = 0; ni < 8; ni++) {
            uint2 lo = make_uint2(f2tf(s[ni][0]), f2tf(s[ni][1]));
            uint2 hi = make_uint2(f2tf(s[ni][2]), f2tf(s[ni][3]));
            *(uint2*)((uint32_t*)Ps + (qw + g) * 64 + SWG(ni, g) + 2 * t4) = lo;
            *(uint2*)((uint32_t*)Ps + (qw + g + 8) * 64 + SWG(ni, g) + 2 * t4) = hi;
        }
        __syncwarp();

        // ---- O += P V (both operands identity key order within k8 groups) ----
        #pragma unroll
        for (int kg = 0; kg < 8; kg++) {
            uint2 a02 = *(uint2*)((uint32_t*)Ps + (qw + g) * 64 + SWG(kg, g) + 2 * t4);
            uint2 a13 = *(uint2*)((uint32_t*)Ps + (qw + g + 8) * 64 + SWG(kg, g) + 2 * t4);
            #pragma unroll
            for (int ni = 0; ni < 8; ni++) {
                uint2 bf = *(uint2*)((uint32_t*)Vs + (ni * 8 + g) * 64 + SWG(kg, g) + 2 * t4);
                mma8(O[ni], a02.x, a13.x, a02.y, a13.y, bf.x, bf.y);
            }
        }
    }

    // ---- epilogue ----
    int r0 = qb + qw + g, r1 = r0 + 8;
    float qm0 = (qmask[b * QQ + r0] != 0) ? 1.0f : 0.0f;
    float qm1 = (qmask[b * QQ + r1] != 0) ? 1.0f : 0.0f;
    float inv0 = qm0 / lr[0], inv1 = qm1 / lr[1];
    #pragma unroll
    for (int ni = 0; ni < 8; ni++) {
        int c = h * 64 + ni * 8 + 2 * t4;
        *(float2*)(AV + (qrow0 + qw + g) * 512 + c) =
            make_float2(O[ni][0] * inv0, O[ni][1] * inv0);
        *(float2*)(AV + (qrow0 + qw + g + 8) * 512 + c) =
            make_float2(O[ni][2] * inv1, O[ni][3] * inv1);
    }
}

// ---------------- launch ------------------------------------------------------
extern "C" void kernel_launch(void* const* d_in, const int* in_sizes, int n_in,
                              void* d_out, int out_size) {
    const float* query = (const float*)d_in[0];
    const float* key   = (const float*)d_in[1];
    const float* value = (const float*)d_in[2];
    const float* wq    = (const float*)d_in[3];
    const float* wk    = (const float*)d_in[4];
    const float* wv    = (const float*)d_in[5];
    const float* wo    = (const float*)d_in[6];
    const float* gw    = (const float*)d_in[7];
    const float* gb    = (const float*)d_in[8];
    const float* qg    = (const float*)d_in[9];
    const float* qbv   = (const float*)d_in[10];
    const float* kg    = (const float*)d_in[11];
    const float* kbv   = (const float*)d_in[12];
    const float* vg    = (const float*)d_in[13];
    const float* vbv   = (const float*)d_in[14];
    const int* qmask   = (const int*)d_in[15];
    const int* kmask   = (const int*)d_in[16];
    float* out = (float*)d_out;

    float *QN, *KN, *VN, *QH, *KH, *VH, *AV, *AVO;
    float *Pq, *Pk, *Pv, *Po, *Pg;
    cudaGetSymbolAddress((void**)&QN,  g_QN);
    cudaGetSymbolAddress((void**)&KN,  g_KN);
    cudaGetSymbolAddress((void**)&VN,  g_VN);
    cudaGetSymbolAddress((void**)&QH,  g_QH);
    cudaGetSymbolAddress((void**)&KH,  g_KH);
    cudaGetSymbolAddress((void**)&VH,  g_VH);
    cudaGetSymbolAddress((void**)&AV,  g_AV);
    cudaGetSymbolAddress((void**)&AVO, g_AVO);
    cudaGetSymbolAddress((void**)&Pq,  g_Pq);
    cudaGetSymbolAddress((void**)&Pk,  g_Pk);
    cudaGetSymbolAddress((void**)&Pv,  g_Pv);
    cudaGetSymbolAddress((void**)&Po,  g_Po);
    cudaGetSymbolAddress((void**)&Pg,  g_Pg);

    cudaFuncSetAttribute(attn_kernel, cudaFuncAttributeMaxDynamicSharedMemorySize, ATT_SMEM);
    cudaFuncSetAttribute(mm_qkv, cudaFuncAttributeMaxDynamicSharedMemorySize, GEMM_SMEM);
    cudaFuncSetAttribute(mm_single, cudaFuncAttributeMaxDynamicSharedMemorySize, GEMM_SMEM);
    cudaFuncSetAttribute(mm_gnet, cudaFuncAttributeMaxDynamicSharedMemorySize, GEMM_SMEM);

    // 0) weight prep (transpose + fragment-permute + tf32 convert), one launch
    prep_w<<<dim3(32, 16, 5), dim3(32, 8)>>>(wq, wk, wv, wo, gw, Pq, Pk, Pv, Po, Pg);

    // 1) pre-layernorm (merged)
    ln3_kernel<<<dim3(BB * KP, 3), 128>>>(query, key, value, qg, qbv, kg, kbv,
                                          vg, vbv, QN, KN, VN);

    // 2) projections (merged QKV, tf32 warp MMA, prepped weights)
    mm_qkv<<<dim3(4, 65, 3), 256, GEMM_SMEM>>>(QN, KN, VN, Pq, Pk, Pv, QH, KH, VH);

    // 3) flash attention
    attn_kernel<<<dim3(QQ / 128, NH, BB), 256, ATT_SMEM>>>(QH, KH, VH, kmask, qmask, AV);

    // 4) output projection
    mm_single<<<dim3(4, 64), 256, GEMM_SMEM>>>(AV, Po, AVO, BB * QQ);

    // 5) g_net + gate + residual
    mm_gnet<<<dim3(4, 64), 256, GEMM_SMEM>>>(query, AVO, Pg, gb, out);
}

// round 12
// speedup vs baseline: 1.7090x; 1.7090x over previous
#include <cuda_runtime.h>
#include <math.h>
#include <stdint.h>

#define BB   2
#define QQ   2048
#define KLEN 2048
#define KP   2049
#define DD   512
#define NH   8
#define HD   64
#define SCALE_F   0.125f
#define NEG_INF_F -1e30f
#define LN_EPS_F  1e-5f

// ---------------- tf32 mma helpers -------------------------------------------
__device__ __forceinline__ uint32_t f2tf(float f) {
    uint32_t u; asm("cvt.rna.tf32.f32 %0, %1;" : "=r"(u) : "f"(f)); return u;
}
__device__ __forceinline__ void mma8(float c[4], uint32_t a0, uint32_t a1,
                                     uint32_t a2, uint32_t a3,
                                     uint32_t b0, uint32_t b1) {
    asm volatile("mma.sync.aligned.m16n8k8.row.col.f32.tf32.tf32.f32 "
        "{%0,%1,%2,%3}, {%4,%5,%6,%7}, {%8,%9}, {%0,%1,%2,%3};"
        : "+f"(c[0]), "+f"(c[1]), "+f"(c[2]), "+f"(c[3])
        : "r"(a0), "r"(a1), "r"(a2), "r"(a3), "r"(b0), "r"(b1));
}

// fragment k-permutation within a k8 group: p = ((kk&3)<<1)|(kk>>2)
#define KPERM(kk) ((((kk) & 3) << 1) | ((kk) >> 2))
// XOR swizzle of k-group by row (rows stride multiple of 32 words)
#define SWG(kg, r) ((((kg) ^ ((r) & 3)) << 3))

// ---------------- scratch ----------------------------------------------------
__device__ float g_QN[BB * QQ * DD];
__device__ float g_KN[BB * KP * DD];
__device__ float g_VN[BB * KP * DD];
__device__ float g_QH[BB * QQ * DD];
__device__ float g_KH[BB * KP * DD];
__device__ float g_VH[BB * KP * DD];
__device__ float g_AV[BB * QQ * DD];
__device__ float g_AVO[BB * QQ * DD];
// prepped weights: tf32 bits, layout [(kt*512 + n)*32 + (kg*8 + KPERM(kk))]
__device__ float g_Pq[DD * DD];
__device__ float g_Pk[DD * DD];
__device__ float g_Pv[DD * DD];
__device__ float g_Po[DD * DD];
__device__ float g_Pg[2 * DD * DD];

// ---------------- weight prep: transpose + permute + tf32-convert -------------
__global__ void prep_w(const float* __restrict__ wq, const float* __restrict__ wk,
                       const float* __restrict__ wv, const float* __restrict__ wo,
                       const float* __restrict__ gw,
                       float* __restrict__ Pq, float* __restrict__ Pk,
                       float* __restrict__ Pv, float* __restrict__ Po,
                       float* __restrict__ Pg) {
    int z = blockIdx.z;
    const float* W = (z == 0) ? wq : (z == 1) ? wk : (z == 2) ? wv
                   : (z == 3) ? wo : gw;
    float* P       = (z == 0) ? Pq : (z == 1) ? Pk : (z == 2) ? Pv
                   : (z == 3) ? Po : Pg;
    int K = (z == 4) ? 1024 : 512;
    int kt = blockIdx.x;
    if (kt * 32 >= K) return;
    int n0 = blockIdx.y * 32;

    __shared__ float t[32][33];
    int x = threadIdx.x, y = threadIdx.y;   // block (32, 8)
    #pragma unroll
    for (int i = 0; i < 4; i++)
        t[y + 8 * i][x] = W[(size_t)(kt * 32 + y + 8 * i) * 512 + n0 + x];
    __syncthreads();

    int kg = x >> 3, p = x & 7;
    int kk = ((p & 1) << 2) | (p >> 1);     // inverse of KPERM
    int krow = kg * 8 + kk;
    #pragma unroll
    for (int i = 0; i < 4; i++) {
        int nn = y + 8 * i;
        P[((size_t)(kt * 512) + n0 + nn) * 32 + x] =
            __uint_as_float(f2tf(t[krow][nn]));
    }
}

// ---------------- merged LayerNorm (y selects q/k/v) --------------------------
__global__ void ln3_kernel(const float* __restrict__ xq,
                           const float* __restrict__ xk,
                           const float* __restrict__ xv,
                           const float* __restrict__ qg, const float* __restrict__ qb,
                           const float* __restrict__ kg, const float* __restrict__ kb,
                           const float* __restrict__ vg, const float* __restrict__ vb,
                           float* __restrict__ yq, float* __restrict__ yk,
                           float* __restrict__ yv) {
    int z = blockIdx.y;
    const float* x     = (z == 0) ? xq : (z == 1) ? xk : xv;
    const float* gamma = (z == 0) ? qg : (z == 1) ? kg : vg;
    const float* beta  = (z == 0) ? qb : (z == 1) ? kb : vb;
    float* y           = (z == 0) ? yq : (z == 1) ? yk : yv;
    int rows_in  = (z == 0) ? QQ : KLEN;
    int rows_out = (z == 0) ? QQ : KP;

    int r = blockIdx.x;
    if (r >= BB * rows_out) return;
    int b = r / rows_out;
    int j = r - b * rows_out;
    int t = threadIdx.x;

    float4 g4 = ((const float4*)gamma)[t];
    float4 b4 = ((const float4*)beta)[t];
    float4* yr = (float4*)(y + (size_t)r * DD);

    if (j >= rows_in) { yr[t] = b4; return; }

    const float4* xr = (const float4*)(x + ((size_t)b * rows_in + j) * DD);
    float4 v = xr[t];
    float s  = v.x + v.y + v.z + v.w;
    float sq = v.x*v.x + v.y*v.y + v.z*v.z + v.w*v.w;
    #pragma unroll
    for (int o = 16; o > 0; o >>= 1) {
        s  += __shfl_xor_sync(0xffffffffu, s,  o);
        sq += __shfl_xor_sync(0xffffffffu, sq, o);
    }
    __shared__ float rs[4], rq[4];
    int w = t >> 5;
    if ((t & 31) == 0) { rs[w] = s; rq[w] = sq; }
    __syncthreads();
    s  = rs[0] + rs[1] + rs[2] + rs[3];
    sq = rq[0] + rq[1] + rq[2] + rq[3];

    float mean = s * (1.0f / DD);
    float var  = sq * (1.0f / DD) - mean * mean;
    float rstd = rsqrtf(var + LN_EPS_F);

    float4 o;
    o.x = (v.x - mean) * rstd * g4.x + b4.x;
    o.y = (v.y - mean) * rstd * g4.y + b4.y;
    o.z = (v.z - mean) * rstd * g4.z + b4.z;
    o.w = (v.w - mean) * rstd * g4.w + b4.w;
    yr[t] = o;
}

// ---------------- tf32 warp-MMA GEMM body -------------------------------------
// BM=64, BN=128, BK=32; 256 thr = 8 warps (2m x 4n), warp tile 32x32.
// XOR-swizzled smem (stride 32 words): conflict-free fragment LDS.64.
#define GEMM_SMEM ((2 * 64 * 32 + 2 * 128 * 32) * 4)

extern __shared__ float smf[];

__device__ __forceinline__ void gemm_body(const float* __restrict__ A,
                                          const float* __restrict__ P,
                                          float* __restrict__ C, int M,
                                          int n0, int m0) {
    float* As0 = smf;
    float* As1 = smf + 64 * 32;
    float* Bs0 = smf + 2 * 64 * 32;
    float* Bs1 = smf + 2 * 64 * 32 + 128 * 32;
    int tid = threadIdx.x;
    int lane = tid & 31, wid = tid >> 5;
    int g = lane >> 2, t4 = lane & 3;
    int mw = wid & 1, nw = wid >> 1;

    float acc[2][4][4] = {};
    float4 ra[2], rb[4];

    auto ldg = [&](int kt) {
        int k0 = kt * 32;
        #pragma unroll
        for (int it = 0; it < 2; it++) {
            int f = tid + it * 256;            // 0..511
            int r = f >> 3; int c4 = f & 7;
            int gm = m0 + r; if (gm > M - 1) gm = M - 1;
            ra[it] = *(const float4*)(A + (size_t)gm * 512 + k0 + c4 * 4);
        }
        const float* Pb = P + ((size_t)kt * 512 + n0) * 32;
        #pragma unroll
        for (int it = 0; it < 4; it++) {
            int f = tid + it * 256;            // 0..1023
            int nr = f >> 3; int c4 = f & 7;
            rb[it] = *(const float4*)(Pb + (size_t)nr * 32 + c4 * 4);
        }
    };
    auto sts = [&](float* Ab, float* Bb) {
        #pragma unroll
        for (int it = 0; it < 2; it++) {
            int f = tid + it * 256;
            int r = f >> 3; int c4 = f & 7;
            float va[4] = {ra[it].x, ra[it].y, ra[it].z, ra[it].w};
            #pragma unroll
            for (int i = 0; i < 4; i++) {
                int k = c4 * 4 + i;
                ((uint32_t*)Ab)[r * 32 + SWG(k >> 3, r) + KPERM(k & 7)] = f2tf(va[i]);
            }
        }
        #pragma unroll
        for (int it = 0; it < 4; it++) {
            int f = tid + it * 256;
            int nr = f >> 3; int c4 = f & 7;
            *(float4*)&Bb[nr * 32 + SWG(c4 >> 1, nr) + (c4 & 1) * 4] = rb[it];
        }
    };
    auto compute = [&](float* Ab, float* Bb) {
        #pragma unroll
        for (int kg = 0; kg < 4; kg++) {
            uint2 a02[2], a13[2];
            #pragma unroll
            for (int mi = 0; mi < 2; mi++) {
                int r = mw * 32 + mi * 16 + g;
                a02[mi] = *(uint2*)((uint32_t*)Ab + r * 32 + SWG(kg, g) + 2 * t4);
                a13[mi] = *(uint2*)((uint32_t*)Ab + (r + 8) * 32 + SWG(kg, g) + 2 * t4);
            }
            #pragma unroll
            for (int ni = 0; ni < 4; ni++) {
                int nr = nw * 32 + ni * 8 + g;
                uint2 bf = *(uint2*)((uint32_t*)Bb + nr * 32 + SWG(kg, g) + 2 * t4);
                #pragma unroll
                for (int mi = 0; mi < 2; mi++)
                    mma8(acc[mi][ni], a02[mi].x, a13[mi].x, a02[mi].y, a13[mi].y,
                         bf.x, bf.y);
            }
        }
    };

    ldg(0); sts(As0, Bs0); __syncthreads();
    const int T = 16;
    for (int t = 0; t < T; t++) {
        if (t + 1 < T) ldg(t + 1);
        if (t & 1) compute(As1, Bs1); else compute(As0, Bs0);
        if (t + 1 < T) { if (t & 1) sts(As0, Bs0); else sts(As1, Bs1); }
        __syncthreads();
    }

    #pragma unroll
    for (int mi = 0; mi < 2; mi++) {
        int r0 = m0 + mw * 32 + mi * 16 + g;
        #pragma unroll
        for (int ni = 0; ni < 4; ni++) {
            int c = n0 + nw * 32 + ni * 8 + 2 * t4;
            if (r0 < M)
                *(float2*)(C + (size_t)r0 * 512 + c) =
                    make_float2(acc[mi][ni][0], acc[mi][ni][1]);
            if (r0 + 8 < M)
                *(float2*)(C + (size_t)(r0 + 8) * 512 + c) =
                    make_float2(acc[mi][ni][2], acc[mi][ni][3]);
        }
    }
}

// merged QKV projection: blockIdx.z selects which projection
__global__ void __launch_bounds__(256, 2) mm_qkv(const float* __restrict__ QN,
                                                 const float* __restrict__ KN,
                                                 const float* __restrict__ VN,
                                                 const float* __restrict__ Pq,
                                                 const float* __restrict__ Pk,
                                                 const float* __restrict__ Pv,
                                                 float* __restrict__ QH,
                                                 float* __restrict__ KH,
                                                 float* __restrict__ VH) {
    int z = blockIdx.z;
    const float* A = (z == 0) ? QN : (z == 1) ? KN : VN;
    const float* P = (z == 0) ? Pq : (z == 1) ? Pk : Pv;
    float* C       = (z == 0) ? QH : (z == 1) ? KH : VH;
    int M = (z == 0) ? BB * QQ : BB * KP;
    int m0 = blockIdx.y * 64;
    if (m0 >= M) return;
    gemm_body(A, P, C, M, blockIdx.x * 128, m0);
}

__global__ void __launch_bounds__(256, 2) mm_single(const float* __restrict__ A,
                                                    const float* __restrict__ P,
                                                    float* __restrict__ C, int M) {
    gemm_body(A, P, C, M, blockIdx.x * 128, blockIdx.y * 64);
}

// ---------------- g_net GEMM (K=1024, prepped weights) + gated residual -------
__global__ void __launch_bounds__(256, 2) mm_gnet(const float* __restrict__ Aq,
                                                  const float* __restrict__ Av,
                                                  const float* __restrict__ Pg,
                                                  const float* __restrict__ gbv,
                                                  float* __restrict__ out) {
    float* As0 = smf;
    float* As1 = smf + 64 * 32;
    float* Bs0 = smf + 2 * 64 * 32;
    float* Bs1 = smf + 2 * 64 * 32 + 128 * 32;
    int tid = threadIdx.x;
    int lane = tid & 31, wid = tid >> 5;
    int g = lane >> 2, t4 = lane & 3;
    int mw = wid & 1, nw = wid >> 1;
    int n0 = blockIdx.x * 128, m0 = blockIdx.y * 64;

    float acc[2][4][4] = {};
    float4 ra[2], rb[4];

    auto ldg = [&](int kt) {
        const float* Ap = (kt < 16) ? Aq : Av;
        int ka = (kt & 15) * 32;
        #pragma unroll
        for (int it = 0; it < 2; it++) {
            int f = tid + it * 256;
            int r = f >> 3; int c4 = f & 7;
            ra[it] = *(const float4*)(Ap + (size_t)(m0 + r) * 512 + ka + c4 * 4);
        }
        const float* Pb = Pg + ((size_t)kt * 512 + n0) * 32;
        #pragma unroll
        for (int it = 0; it < 4; it++) {
            int f = tid + it * 256;
            int nr = f >> 3; int c4 = f & 7;
            rb[it] = *(const float4*)(Pb + (size_t)nr * 32 + c4 * 4);
        }
    };
    auto sts = [&](float* Ab, float* Bb) {
        #pragma unroll
        for (int it = 0; it < 2; it++) {
            int f = tid + it * 256;
            int r = f >> 3; int c4 = f & 7;
            float va[4] = {ra[it].x, ra[it].y, ra[it].z, ra[it].w};
            #pragma unroll
            for (int i = 0; i < 4; i++) {
                int k = c4 * 4 + i;
                ((uint32_t*)Ab)[r * 32 + SWG(k >> 3, r) + KPERM(k & 7)] = f2tf(va[i]);
            }
        }
        #pragma unroll
        for (int it = 0; it < 4; it++) {
            int f = tid + it * 256;
            int nr = f >> 3; int c4 = f & 7;
            *(float4*)&Bb[nr * 32 + SWG(c4 >> 1, nr) + (c4 & 1) * 4] = rb[it];
        }
    };
    auto compute = [&](float* Ab, float* Bb) {
        #pragma unroll
        for (int kg = 0; kg < 4; kg++) {
            uint2 a02[2], a13[2];
            #pragma unroll
            for (int mi = 0; mi < 2; mi++) {
                int r = mw * 32 + mi * 16 + g;
                a02[mi] = *(uint2*)((uint32_t*)Ab + r * 32 + SWG(kg, g) + 2 * t4);
                a13[mi] = *(uint2*)((uint32_t*)Ab + (r + 8) * 32 + SWG(kg, g) + 2 * t4);
            }
            #pragma unroll
            for (int ni = 0; ni < 4; ni++) {
                int nr = nw * 32 + ni * 8 + g;
                uint2 bf = *(uint2*)((uint32_t*)Bb + nr * 32 + SWG(kg, g) + 2 * t4);
                #pragma unroll
                for (int mi = 0; mi < 2; mi++)
                    mma8(acc[mi][ni], a02[mi].x, a13[mi].x, a02[mi].y, a13[mi].y,
                         bf.x, bf.y);
            }
        }
    };

    ldg(0); sts(As0, Bs0); __syncthreads();
    const int T = 32;
    for (int t = 0; t < T; t++) {
        if (t + 1 < T) ldg(t + 1);
        if (t & 1) compute(As1, Bs1); else compute(As0, Bs0);
        if (t + 1 < T) { if (t & 1) sts(As0, Bs0); else sts(As1, Bs1); }
        __syncthreads();
    }

    #pragma unroll
    for (int mi = 0; mi < 2; mi++) {
        int r0 = m0 + mw * 32 + mi * 16 + g;
        #pragma unroll
        for (int ni = 0; ni < 4; ni++) {
            int c = n0 + nw * 32 + ni * 8 + 2 * t4;
            float2 bb = *(const float2*)(gbv + c);
            #pragma unroll
            for (int sel = 0; sel < 2; sel++) {
                size_t r = r0 + sel * 8;
                float2 qv = *(const float2*)(Aq + r * 512 + c);
                float2 av = *(const float2*)(Av + r * 512 + c);
                float s0 = acc[mi][ni][sel * 2 + 0] + bb.x;
                float s1 = acc[mi][ni][sel * 2 + 1] + bb.y;
                float g0 = 1.0f / (1.0f + __expf(-s0));
                float g1 = 1.0f / (1.0f + __expf(-s1));
                float o0 = qv.x + g0 * qv.x + (1.0f - g0) * av.x;
                float o1 = qv.y + g1 * qv.y + (1.0f - g1) * av.y;
                *(float2*)(out + r * 512 + c) = make_float2(o0, o1);
            }
        }
    }
}

// ---------------- flash attention: register-direct PV (no P SMEM round-trip) --
// Buffers stride 64 words: Qs[128] Ks[64] Vs[64] + Ms[64]. 65.8KB -> 2 CTA/SM.
// PV mma A-fragment comes straight from the QK^T C-fragment registers; V uses
// IDENTITY within-group key placement so both operands agree on k-order.
#define ATT_SMEM (((128 + 64 + 64) * 64 + 64) * 4)

__global__ void __launch_bounds__(256, 2) attn_kernel(const float* __restrict__ QHp,
                                                      const float* __restrict__ KHp,
                                                      const float* __restrict__ VHp,
                                                      const int* __restrict__ kmask,
                                                      const int* __restrict__ qmask,
                                                      float* __restrict__ AV) {
    float* Qs = smf;                 // [128][64] tf32, swizzled (KPERM over d)
    float* Ks = Qs + 128 * 64;       // [64][64]  rows=keys, cols=d (KPERM)
    float* Vs = Ks + 64 * 64;        // [64][64]  rows=d,    cols=keys (identity)
    float* Ms = Vs + 64 * 64;        // [64]

    int tid = threadIdx.x;
    int lane = tid & 31, wid = tid >> 5;
    int g = lane >> 2, t4 = lane & 3;
    int qw = wid * 16;
    int qb = blockIdx.x * 128, h = blockIdx.y, b = blockIdx.z;
    size_t qrow0 = (size_t)b * QQ + qb;

    // stage Q (pre-scaled, tf32, swizzled, KPERM over d)
    #pragma unroll
    for (int it = 0; it < 8; it++) {
        int f = tid + it * 256; int q = f >> 4; int c4 = f & 15;
        float4 v = *(const float4*)(QHp + (qrow0 + q) * 512 + h * 64 + c4 * 4);
        float va[4] = {v.x * SCALE_F, v.y * SCALE_F, v.z * SCALE_F, v.w * SCALE_F};
        #pragma unroll
        for (int i = 0; i < 4; i++) {
            int d = c4 * 4 + i;
            ((uint32_t*)Qs)[q * 64 + SWG(d >> 3, q) + KPERM(d & 7)] = f2tf(va[i]);
        }
    }

    float mr[2] = {NEG_INF_F, NEG_INF_F};
    float lr[2] = {0.f, 0.f};
    float O[8][4] = {};

    for (int t0 = 0; t0 < KP; t0 += 64) {
        __syncthreads();
        // ---- stage K (row=key, col=d swizzled KPERM; coalesced LDG) ----
        #pragma unroll
        for (int it = 0; it < 4; it++) {
            int f = tid + it * 256; int j = f >> 4; int c4 = f & 15;
            int jg = t0 + j;
            float4 kv = make_float4(0.f, 0.f, 0.f, 0.f);
            if (jg < KP)
                kv = *(const float4*)(KHp + ((size_t)b * KP + jg) * 512 + h * 64 + c4 * 4);
            float ka[4] = {kv.x, kv.y, kv.z, kv.w};
            #pragma unroll
            for (int i = 0; i < 4; i++) {
                int d = c4 * 4 + i;
                ((uint32_t*)Ks)[j * 64 + SWG(d >> 3, j) + KPERM(d & 7)] = f2tf(ka[i]);
            }
        }
        // ---- stage V transposed (row=d, col=key IDENTITY within group) ----
        #pragma unroll
        for (int it = 0; it < 4; it++) {
            int f = tid + it * 256; int j6 = f & 63; int dc = f >> 6;
            int jg = t0 + j6;
            float4 vv = make_float4(0.f, 0.f, 0.f, 0.f);
            if (jg < KP)
                vv = *(const float4*)(VHp + ((size_t)b * KP + jg) * 512 + h * 64 + dc * 4);
            float va[4] = {vv.x, vv.y, vv.z, vv.w};
            #pragma unroll
            for (int i = 0; i < 4; i++) {
                int d = dc * 4 + i;
                ((uint32_t*)Vs)[d * 64 + SWG(j6 >> 3, d) + (j6 & 7)] = f2tf(va[i]);
            }
        }
        if (tid < 64) {
            int jg = t0 + tid;
            bool valid = (jg < KLEN) ? (kmask[b * KLEN + jg] != 0) : (jg == KLEN);
            Ms[tid] = valid ? 0.0f : NEG_INF_F;
        }
        __syncthreads();

        // ---- S = Q K^T ----
        float s[8][4] = {};
        #pragma unroll
        for (int kg = 0; kg < 8; kg++) {
            uint2 a02 = *(uint2*)((uint32_t*)Qs + (qw + g) * 64 + SWG(kg, g) + 2 * t4);
            uint2 a13 = *(uint2*)((uint32_t*)Qs + (qw + g + 8) * 64 + SWG(kg, g) + 2 * t4);
            #pragma unroll
            for (int ni = 0; ni < 8; ni++) {
                uint2 bf = *(uint2*)((uint32_t*)Ks + (ni * 8 + g) * 64 + SWG(kg, g) + 2 * t4);
                mma8(s[ni], a02.x, a13.x, a02.y, a13.y, bf.x, bf.y);
            }
        }
        // mask
        #pragma unroll
        for (int ni = 0; ni < 8; ni++) {
            float2 mk = *(float2*)&Ms[ni * 8 + 2 * t4];
            s[ni][0] += mk.x; s[ni][1] += mk.y;
            s[ni][2] += mk.x; s[ni][3] += mk.y;
        }
        // ---- online softmax ----
        float mx0 = NEG_INF_F, mx1 = NEG_INF_F;
        #pragma unroll
        for (int ni = 0; ni < 8; ni++) {
            mx0 = fmaxf(mx0, fmaxf(s[ni][0], s[ni][1]));
            mx1 = fmaxf(mx1, fmaxf(s[ni][2], s[ni][3]));
        }
        mx0 = fmaxf(mx0, __shfl_xor_sync(0xffffffffu, mx0, 1));
        mx0 = fmaxf(mx0, __shfl_xor_sync(0xffffffffu, mx0, 2));
        mx1 = fmaxf(mx1, __shfl_xor_sync(0xffffffffu, mx1, 1));
        mx1 = fmaxf(mx1, __shfl_xor_sync(0xffffffffu, mx1, 2));
        float mn0 = fmaxf(mr[0], mx0), mn1 = fmaxf(mr[1], mx1);
        float al0 = __expf(mr[0] - mn0), al1 = __expf(mr[1] - mn1);
        float sum0 = 0.f, sum1 = 0.f;
        #pragma unroll
        for (int ni = 0; ni < 8; ni++) {
            s[ni][0] = __expf(s[ni][0] - mn0); sum0 += s[ni][0];
            s[ni][1] = __expf(s[ni][1] - mn0); sum0 += s[ni][1];
            s[ni][2] = __expf(s[ni][2] - mn1); sum1 += s[ni][2];
            s[ni][3] = __expf(s[ni][3] - mn1); sum1 += s[ni][3];
        }
        sum0 += __shfl_xor_sync(0xffffffffu, sum0, 1);
        sum0 += __shfl_xor_sync(0xffffffffu, sum0, 2);
        sum1 += __shfl_xor_sync(0xffffffffu, sum1, 1);
        sum1 += __shfl_xor_sync(0xffffffffu, sum1, 2);
        lr[0] = lr[0] * al0 + sum0;
        lr[1] = lr[1] * al1 + sum1;
        mr[0] = mn0; mr[1] = mn1;
        #pragma unroll
        for (int ni = 0; ni < 8; ni++) {
            O[ni][0] *= al0; O[ni][1] *= al0;
            O[ni][2] *= al1; O[ni][3] *= al1;
        }

        // ---- O += P V : A-fragment DIRECT from QK^T C-fragment registers ----
        // C frag: keys (kg*8+2t4, +2t4+1) for rows qw+g / qw+g+8.
        // A slots: t4 <- key 2t4 (s[kg][0]/s[kg][2]); t4+4 <- key 2t4+1 (s[kg][1]/s[kg][3]).
        // V identity placement puts key 2t4 -> B slot t4, key 2t4+1 -> slot t4+4: consistent.
        #pragma unroll
        for (int kg = 0; kg < 8; kg++) {
            uint32_t pa0 = f2tf(s[kg][0]);
            uint32_t pa1 = f2tf(s[kg][2]);
            uint32_t pa2 = f2tf(s[kg][1]);
            uint32_t pa3 = f2tf(s[kg][3]);
            #pragma unroll
            for (int ni = 0; ni < 8; ni++) {
                uint2 bf = *(uint2*)((uint32_t*)Vs + (ni * 8 + g) * 64 + SWG(kg, g) + 2 * t4);
                mma8(O[ni], pa0, pa1, pa2, pa3, bf.x, bf.y);
            }
        }
    }

    // ---- epilogue ----
    int r0 = qb + qw + g, r1 = r0 + 8;
    float qm0 = (qmask[b * QQ + r0] != 0) ? 1.0f : 0.0f;
    float qm1 = (qmask[b * QQ + r1] != 0) ? 1.0f : 0.0f;
    float inv0 = qm0 / lr[0], inv1 = qm1 / lr[1];
    #pragma unroll
    for (int ni = 0; ni < 8; ni++) {
        int c = h * 64 + ni * 8 + 2 * t4;
        *(float2*)(AV + (qrow0 + qw + g) * 512 + c) =
            make_float2(O[ni][0] * inv0, O[ni][1] * inv0);
        *(float2*)(AV + (qrow0 + qw + g + 8) * 512 + c) =
            make_float2(O[ni][2] * inv1, O[ni][3] * inv1);
    }
}

// ---------------- launch ------------------------------------------------------
extern "C" void kernel_launch(void* const* d_in, const int* in_sizes, int n_in,
                              void* d_out, int out_size) {
    const float* query = (const float*)d_in[0];
    const float* key   = (const float*)d_in[1];
    const float* value = (const float*)d_in[2];
    const float* wq    = (const float*)d_in[3];
    const float* wk    = (const float*)d_in[4];
    const float* wv    = (const float*)d_in[5];
    const float* wo    = (const float*)d_in[6];
    const float* gw    = (const float*)d_in[7];
    const float* gb    = (const float*)d_in[8];
    const float* qg    = (const float*)d_in[9];
    const float* qbv   = (const float*)d_in[10];
    const float* kg    = (const float*)d_in[11];
    const float* kbv   = (const float*)d_in[12];
    const float* vg    = (const float*)d_in[13];
    const float* vbv   = (const float*)d_in[14];
    const int* qmask   = (const int*)d_in[15];
    const int* kmask   = (const int*)d_in[16];
    float* out = (float*)d_out;

    float *QN, *KN, *VN, *QH, *KH, *VH, *AV, *AVO;
    float *Pq, *Pk, *Pv, *Po, *Pg;
    cudaGetSymbolAddress((void**)&QN,  g_QN);
    cudaGetSymbolAddress((void**)&KN,  g_KN);
    cudaGetSymbolAddress((void**)&VN,  g_VN);
    cudaGetSymbolAddress((void**)&QH,  g_QH);
    cudaGetSymbolAddress((void**)&KH,  g_KH);
    cudaGetSymbolAddress((void**)&VH,  g_VH);
    cudaGetSymbolAddress((void**)&AV,  g_AV);
    cudaGetSymbolAddress((void**)&AVO, g_AVO);
    cudaGetSymbolAddress((void**)&Pq,  g_Pq);
    cudaGetSymbolAddress((void**)&Pk,  g_Pk);
    cudaGetSymbolAddress((void**)&Pv,  g_Pv);
    cudaGetSymbolAddress((void**)&Po,  g_Po);
    cudaGetSymbolAddress((void**)&Pg,  g_Pg);

    cudaFuncSetAttribute(attn_kernel, cudaFuncAttributeMaxDynamicSharedMemorySize, ATT_SMEM);
    cudaFuncSetAttribute(mm_qkv, cudaFuncAttributeMaxDynamicSharedMemorySize, GEMM_SMEM);
    cudaFuncSetAttribute(mm_single, cudaFuncAttributeMaxDynamicSharedMemorySize, GEMM_SMEM);
    cudaFuncSetAttribute(mm_gnet, cudaFuncAttributeMaxDynamicSharedMemorySize, GEMM_SMEM);

    // 0) weight prep (transpose + fragment-permute + tf32 convert), one launch
    prep_w<<<dim3(32, 16, 5), dim3(32, 8)>>>(wq, wk, wv, wo, gw, Pq, Pk, Pv, Po, Pg);

    // 1) pre-layernorm (merged)
    ln3_kernel<<<dim3(BB * KP, 3), 128>>>(query, key, value, qg, qbv, kg, kbv,
                                          vg, vbv, QN, KN, VN);

    // 2) projections (merged QKV, tf32 warp MMA, prepped weights)
    mm_qkv<<<dim3(4, 65, 3), 256, GEMM_SMEM>>>(QN, KN, VN, Pq, Pk, Pv, QH, KH, VH);

    // 3) flash attention (register-direct PV)
    attn_kernel<<<dim3(QQ / 128, NH, BB), 256, ATT_SMEM>>>(QH, KH, VH, kmask, qmask, AV);

    // 4) output projection
    mm_single<<<dim3(4, 64), 256, GEMM_SMEM>>>(AV, Po, AVO, BB * QQ);

    // 5) g_net + gate + residual
    mm_gnet<<<dim3(4, 64), 256, GEMM_SMEM>>>(query, AVO, Pg, gb, out);
}

// round 13
// speedup vs baseline: 1.7103x; 1.0007x over previous
#include <cuda_runtime.h>
#include <math.h>
#include <stdint.h>

#define BB   2
#define QQ   2048
#define KLEN 2048
#define KP   2049
#define DD   512
#define NH   8
#define HD   64
#define SCALE_F   0.125f
#define NEG_INF_F -1e30f
#define LN_EPS_F  1e-5f

// ---------------- tf32 mma helpers -------------------------------------------
__device__ __forceinline__ uint32_t f2tf(float f) {
    uint32_t u; asm("cvt.rna.tf32.f32 %0, %1;" : "=r"(u) : "f"(f)); return u;
}
__device__ __forceinline__ void mma8(float c[4], uint32_t a0, uint32_t a1,
                                     uint32_t a2, uint32_t a3,
                                     uint32_t b0, uint32_t b1) {
    asm volatile("mma.sync.aligned.m16n8k8.row.col.f32.tf32.tf32.f32 "
        "{%0,%1,%2,%3}, {%4,%5,%6,%7}, {%8,%9}, {%0,%1,%2,%3};"
        : "+f"(c[0]), "+f"(c[1]), "+f"(c[2]), "+f"(c[3])
        : "r"(a0), "r"(a1), "r"(a2), "r"(a3), "r"(b0), "r"(b1));
}

// fragment k-permutation within a k8 group: p = ((kk&3)<<1)|(kk>>2)
#define KPERM(kk) ((((kk) & 3) << 1) | ((kk) >> 2))
// XOR swizzle of k-group by row (rows stride multiple of 32 words)
#define SWG(kg, r) ((((kg) ^ ((r) & 3)) << 3))

// ---------------- scratch ----------------------------------------------------
__device__ float g_QN[BB * QQ * DD];
__device__ float g_KN[BB * KP * DD];
__device__ float g_VN[BB * KP * DD];
__device__ float g_QH[BB * QQ * DD];
__device__ float g_KH[BB * KP * DD];
__device__ float g_VH[BB * KP * DD];
__device__ float g_AV[BB * QQ * DD];
__device__ float g_AVO[BB * QQ * DD];
// prepped weights: tf32 bits, layout [(kt*512 + n)*32 + (kg*8 + KPERM(kk))]
__device__ float g_Pq[DD * DD];
__device__ float g_Pk[DD * DD];
__device__ float g_Pv[DD * DD];
__device__ float g_Po[DD * DD];
__device__ float g_Pg[2 * DD * DD];

// ---------------- weight prep: transpose + permute + tf32-convert -------------
__global__ void prep_w(const float* __restrict__ wq, const float* __restrict__ wk,
                       const float* __restrict__ wv, const float* __restrict__ wo,
                       const float* __restrict__ gw,
                       float* __restrict__ Pq, float* __restrict__ Pk,
                       float* __restrict__ Pv, float* __restrict__ Po,
                       float* __restrict__ Pg) {
    int z = blockIdx.z;
    const float* W = (z == 0) ? wq : (z == 1) ? wk : (z == 2) ? wv
                   : (z == 3) ? wo : gw;
    float* P       = (z == 0) ? Pq : (z == 1) ? Pk : (z == 2) ? Pv
                   : (z == 3) ? Po : Pg;
    int K = (z == 4) ? 1024 : 512;
    int kt = blockIdx.x;
    if (kt * 32 >= K) return;
    int n0 = blockIdx.y * 32;

    __shared__ float t[32][33];
    int x = threadIdx.x, y = threadIdx.y;   // block (32, 8)
    #pragma unroll
    for (int i = 0; i < 4; i++)
        t[y + 8 * i][x] = W[(size_t)(kt * 32 + y + 8 * i) * 512 + n0 + x];
    __syncthreads();

    int kg = x >> 3, p = x & 7;
    int kk = ((p & 1) << 2) | (p >> 1);     // inverse of KPERM
    int krow = kg * 8 + kk;
    #pragma unroll
    for (int i = 0; i < 4; i++) {
        int nn = y + 8 * i;
        P[((size_t)(kt * 512) + n0 + nn) * 32 + x] =
            __uint_as_float(f2tf(t[krow][nn]));
    }
}

// ---------------- merged LayerNorm (y selects q/k/v) --------------------------
__global__ void ln3_kernel(const float* __restrict__ xq,
                           const float* __restrict__ xk,
                           const float* __restrict__ xv,
                           const float* __restrict__ qg, const float* __restrict__ qb,
                           const float* __restrict__ kg, const float* __restrict__ kb,
                           const float* __restrict__ vg, const float* __restrict__ vb,
                           float* __restrict__ yq, float* __restrict__ yk,
                           float* __restrict__ yv) {
    int z = blockIdx.y;
    const float* x     = (z == 0) ? xq : (z == 1) ? xk : xv;
    const float* gamma = (z == 0) ? qg : (z == 1) ? kg : vg;
    const float* beta  = (z == 0) ? qb : (z == 1) ? kb : vb;
    float* y           = (z == 0) ? yq : (z == 1) ? yk : yv;
    int rows_in  = (z == 0) ? QQ : KLEN;
    int rows_out = (z == 0) ? QQ : KP;

    int r = blockIdx.x;
    if (r >= BB * rows_out) return;
    int b = r / rows_out;
    int j = r - b * rows_out;
    int t = threadIdx.x;

    float4 g4 = ((const float4*)gamma)[t];
    float4 b4 = ((const float4*)beta)[t];
    float4* yr = (float4*)(y + (size_t)r * DD);

    if (j >= rows_in) { yr[t] = b4; return; }

    const float4* xr = (const float4*)(x + ((size_t)b * rows_in + j) * DD);
    float4 v = xr[t];
    float s  = v.x + v.y + v.z + v.w;
    float sq = v.x*v.x + v.y*v.y + v.z*v.z + v.w*v.w;
    #pragma unroll
    for (int o = 16; o > 0; o >>= 1) {
        s  += __shfl_xor_sync(0xffffffffu, s,  o);
        sq += __shfl_xor_sync(0xffffffffu, sq, o);
    }
    __shared__ float rs[4], rq[4];
    int w = t >> 5;
    if ((t & 31) == 0) { rs[w] = s; rq[w] = sq; }
    __syncthreads();
    s  = rs[0] + rs[1] + rs[2] + rs[3];
    sq = rq[0] + rq[1] + rq[2] + rq[3];

    float mean = s * (1.0f / DD);
    float var  = sq * (1.0f / DD) - mean * mean;
    float rstd = rsqrtf(var + LN_EPS_F);

    float4 o;
    o.x = (v.x - mean) * rstd * g4.x + b4.x;
    o.y = (v.y - mean) * rstd * g4.y + b4.y;
    o.z = (v.z - mean) * rstd * g4.z + b4.z;
    o.w = (v.w - mean) * rstd * g4.w + b4.w;
    yr[t] = o;
}

// ---------------- tf32 warp-MMA GEMM body -------------------------------------
// BM=64, BN=128, BK=32; 256 thr = 8 warps (2m x 4n), warp tile 32x32.
// XOR-swizzled smem (stride 32 words): conflict-free fragment LDS.64.
#define GEMM_SMEM ((2 * 64 * 32 + 2 * 128 * 32) * 4)

extern __shared__ float smf[];

__device__ __forceinline__ void gemm_body(const float* __restrict__ A,
                                          const float* __restrict__ P,
                                          float* __restrict__ C, int M,
                                          int n0, int m0) {
    float* As0 = smf;
    float* As1 = smf + 64 * 32;
    float* Bs0 = smf + 2 * 64 * 32;
    float* Bs1 = smf + 2 * 64 * 32 + 128 * 32;
    int tid = threadIdx.x;
    int lane = tid & 31, wid = tid >> 5;
    int g = lane >> 2, t4 = lane & 3;
    int mw = wid & 1, nw = wid >> 1;

    float acc[2][4][4] = {};
    float4 ra[2], rb[4];

    auto ldg = [&](int kt) {
        int k0 = kt * 32;
        #pragma unroll
        for (int it = 0; it < 2; it++) {
            int f = tid + it * 256;            // 0..511
            int r = f >> 3; int c4 = f & 7;
            int gm = m0 + r; if (gm > M - 1) gm = M - 1;
            ra[it] = *(const float4*)(A + (size_t)gm * 512 + k0 + c4 * 4);
        }
        const float* Pb = P + ((size_t)kt * 512 + n0) * 32;
        #pragma unroll
        for (int it = 0; it < 4; it++) {
            int f = tid + it * 256;            // 0..1023
            int nr = f >> 3; int c4 = f & 7;
            rb[it] = *(const float4*)(Pb + (size_t)nr * 32 + c4 * 4);
        }
    };
    auto sts = [&](float* Ab, float* Bb) {
        #pragma unroll
        for (int it = 0; it < 2; it++) {
            int f = tid + it * 256;
            int r = f >> 3; int c4 = f & 7;
            float va[4] = {ra[it].x, ra[it].y, ra[it].z, ra[it].w};
            #pragma unroll
            for (int i = 0; i < 4; i++) {
                int k = c4 * 4 + i;
                ((uint32_t*)Ab)[r * 32 + SWG(k >> 3, r) + KPERM(k & 7)] = f2tf(va[i]);
            }
        }
        #pragma unroll
        for (int it = 0; it < 4; it++) {
            int f = tid + it * 256;
            int nr = f >> 3; int c4 = f & 7;
            *(float4*)&Bb[nr * 32 + SWG(c4 >> 1, nr) + (c4 & 1) * 4] = rb[it];
        }
    };
    auto compute = [&](float* Ab, float* Bb) {
        #pragma unroll
        for (int kg = 0; kg < 4; kg++) {
            uint2 a02[2], a13[2];
            #pragma unroll
            for (int mi = 0; mi < 2; mi++) {
                int r = mw * 32 + mi * 16 + g;
                a02[mi] = *(uint2*)((uint32_t*)Ab + r * 32 + SWG(kg, g) + 2 * t4);
                a13[mi] = *(uint2*)((uint32_t*)Ab + (r + 8) * 32 + SWG(kg, g) + 2 * t4);
            }
            #pragma unroll
            for (int ni = 0; ni < 4; ni++) {
                int nr = nw * 32 + ni * 8 + g;
                uint2 bf = *(uint2*)((uint32_t*)Bb + nr * 32 + SWG(kg, g) + 2 * t4);
                #pragma unroll
                for (int mi = 0; mi < 2; mi++)
                    mma8(acc[mi][ni], a02[mi].x, a13[mi].x, a02[mi].y, a13[mi].y,
                         bf.x, bf.y);
            }
        }
    };

    ldg(0); sts(As0, Bs0); __syncthreads();
    const int T = 16;
    for (int t = 0; t < T; t++) {
        if (t + 1 < T) ldg(t + 1);
        if (t & 1) compute(As1, Bs1); else compute(As0, Bs0);
        if (t + 1 < T) { if (t & 1) sts(As0, Bs0); else sts(As1, Bs1); }
        __syncthreads();
    }

    #pragma unroll
    for (int mi = 0; mi < 2; mi++) {
        int r0 = m0 + mw * 32 + mi * 16 + g;
        #pragma unroll
        for (int ni = 0; ni < 4; ni++) {
            int c = n0 + nw * 32 + ni * 8 + 2 * t4;
            if (r0 < M)
                *(float2*)(C + (size_t)r0 * 512 + c) =
                    make_float2(acc[mi][ni][0], acc[mi][ni][1]);
            if (r0 + 8 < M)
                *(float2*)(C + (size_t)(r0 + 8) * 512 + c) =
                    make_float2(acc[mi][ni][2], acc[mi][ni][3]);
        }
    }
}

// merged QKV projection: blockIdx.z selects which projection
__global__ void __launch_bounds__(256, 2) mm_qkv(const float* __restrict__ QN,
                                                 const float* __restrict__ KN,
                                                 const float* __restrict__ VN,
                                                 const float* __restrict__ Pq,
                                                 const float* __restrict__ Pk,
                                                 const float* __restrict__ Pv,
                                                 float* __restrict__ QH,
                                                 float* __restrict__ KH,
                                                 float* __restrict__ VH) {
    int z = blockIdx.z;
    const float* A = (z == 0) ? QN : (z == 1) ? KN : VN;
    const float* P = (z == 0) ? Pq : (z == 1) ? Pk : Pv;
    float* C       = (z == 0) ? QH : (z == 1) ? KH : VH;
    int M = (z == 0) ? BB * QQ : BB * KP;
    int m0 = blockIdx.y * 64;
    if (m0 >= M) return;
    gemm_body(A, P, C, M, blockIdx.x * 128, m0);
}

__global__ void __launch_bounds__(256, 2) mm_single(const float* __restrict__ A,
                                                    const float* __restrict__ P,
                                                    float* __restrict__ C, int M) {
    gemm_body(A, P, C, M, blockIdx.x * 128, blockIdx.y * 64);
}

// ---------------- g_net GEMM (K=1024, prepped weights) + gated residual -------
__global__ void __launch_bounds__(256, 2) mm_gnet(const float* __restrict__ Aq,
                                                  const float* __restrict__ Av,
                                                  const float* __restrict__ Pg,
                                                  const float* __restrict__ gbv,
                                                  float* __restrict__ out) {
    float* As0 = smf;
    float* As1 = smf + 64 * 32;
    float* Bs0 = smf + 2 * 64 * 32;
    float* Bs1 = smf + 2 * 64 * 32 + 128 * 32;
    int tid = threadIdx.x;
    int lane = tid & 31, wid = tid >> 5;
    int g = lane >> 2, t4 = lane & 3;
    int mw = wid & 1, nw = wid >> 1;
    int n0 = blockIdx.x * 128, m0 = blockIdx.y * 64;

    float acc[2][4][4] = {};
    float4 ra[2], rb[4];

    auto ldg = [&](int kt) {
        const float* Ap = (kt < 16) ? Aq : Av;
        int ka = (kt & 15) * 32;
        #pragma unroll
        for (int it = 0; it < 2; it++) {
            int f = tid + it * 256;
            int r = f >> 3; int c4 = f & 7;
            ra[it] = *(const float4*)(Ap + (size_t)(m0 + r) * 512 + ka + c4 * 4);
        }
        const float* Pb = Pg + ((size_t)kt * 512 + n0) * 32;
        #pragma unroll
        for (int it = 0; it < 4; it++) {
            int f = tid + it * 256;
            int nr = f >> 3; int c4 = f & 7;
            rb[it] = *(const float4*)(Pb + (size_t)nr * 32 + c4 * 4);
        }
    };
    auto sts = [&](float* Ab, float* Bb) {
        #pragma unroll
        for (int it = 0; it < 2; it++) {
            int f = tid + it * 256;
            int r = f >> 3; int c4 = f & 7;
            float va[4] = {ra[it].x, ra[it].y, ra[it].z, ra[it].w};
            #pragma unroll
            for (int i = 0; i < 4; i++) {
                int k = c4 * 4 + i;
                ((uint32_t*)Ab)[r * 32 + SWG(k >> 3, r) + KPERM(k & 7)] = f2tf(va[i]);
            }
        }
        #pragma unroll
        for (int it = 0; it < 4; it++) {
            int f = tid + it * 256;
            int nr = f >> 3; int c4 = f & 7;
            *(float4*)&Bb[nr * 32 + SWG(c4 >> 1, nr) + (c4 & 1) * 4] = rb[it];
        }
    };
    auto compute = [&](float* Ab, float* Bb) {
        #pragma unroll
        for (int kg = 0; kg < 4; kg++) {
            uint2 a02[2], a13[2];
            #pragma unroll
            for (int mi = 0; mi < 2; mi++) {
                int r = mw * 32 + mi * 16 + g;
                a02[mi] = *(uint2*)((uint32_t*)Ab + r * 32 + SWG(kg, g) + 2 * t4);
                a13[mi] = *(uint2*)((uint32_t*)Ab + (r + 8) * 32 + SWG(kg, g) + 2 * t4);
            }
            #pragma unroll
            for (int ni = 0; ni < 4; ni++) {
                int nr = nw * 32 + ni * 8 + g;
                uint2 bf = *(uint2*)((uint32_t*)Bb + nr * 32 + SWG(kg, g) + 2 * t4);
                #pragma unroll
                for (int mi = 0; mi < 2; mi++)
                    mma8(acc[mi][ni], a02[mi].x, a13[mi].x, a02[mi].y, a13[mi].y,
                         bf.x, bf.y);
            }
        }
    };

    ldg(0); sts(As0, Bs0); __syncthreads();
    const int T = 32;
    for (int t = 0; t < T; t++) {
        if (t + 1 < T) ldg(t + 1);
        if (t & 1) compute(As1, Bs1); else compute(As0, Bs0);
        if (t + 1 < T) { if (t & 1) sts(As0, Bs0); else sts(As1, Bs1); }
        __syncthreads();
    }

    #pragma unroll
    for (int mi = 0; mi < 2; mi++) {
        int r0 = m0 + mw * 32 + mi * 16 + g;
        #pragma unroll
        for (int ni = 0; ni < 4; ni++) {
            int c = n0 + nw * 32 + ni * 8 + 2 * t4;
            float2 bb = *(const float2*)(gbv + c);
            #pragma unroll
            for (int sel = 0; sel < 2; sel++) {
                size_t r = r0 + sel * 8;
                float2 qv = *(const float2*)(Aq + r * 512 + c);
                float2 av = *(const float2*)(Av + r * 512 + c);
                float s0 = acc[mi][ni][sel * 2 + 0] + bb.x;
                float s1 = acc[mi][ni][sel * 2 + 1] + bb.y;
                float g0 = 1.0f / (1.0f + __expf(-s0));
                float g1 = 1.0f / (1.0f + __expf(-s1));
                float o0 = qv.x + g0 * qv.x + (1.0f - g0) * av.x;
                float o1 = qv.y + g1 * qv.y + (1.0f - g1) * av.y;
                *(float2*)(out + r * 512 + c) = make_float2(o0, o1);
            }
        }
    }
}

// ---------------- flash attention: register-direct PV (no P SMEM round-trip) --
// Buffers stride 64 words: Qs[128] Ks[64] Vs[64] + Ms[64]. 65.8KB -> 2 CTA/SM.
// PV mma A-fragment comes straight from the QK^T C-fragment registers; V uses
// IDENTITY within-group key placement so both operands agree on k-order.
#define ATT_SMEM (((128 + 64 + 64) * 64 + 64) * 4)

__global__ void __launch_bounds__(256, 2) attn_kernel(const float* __restrict__ QHp,
                                                      const float* __restrict__ KHp,
                                                      const float* __restrict__ VHp,
                                                      const int* __restrict__ kmask,
                                                      const int* __restrict__ qmask,
                                                      float* __restrict__ AV) {
    float* Qs = smf;                 // [128][64] tf32, swizzled (KPERM over d)
    float* Ks = Qs + 128 * 64;       // [64][64]  rows=keys, cols=d (KPERM)
    float* Vs = Ks + 64 * 64;        // [64][64]  rows=d,    cols=keys (identity)
    float* Ms = Vs + 64 * 64;        // [64]

    int tid = threadIdx.x;
    int lane = tid & 31, wid = tid >> 5;
    int g = lane >> 2, t4 = lane & 3;
    int qw = wid * 16;
    int qb = blockIdx.x * 128, h = blockIdx.y, b = blockIdx.z;
    size_t qrow0 = (size_t)b * QQ + qb;

    // stage Q (pre-scaled, tf32, swizzled, KPERM over d)
    #pragma unroll
    for (int it = 0; it < 8; it++) {
        int f = tid + it * 256; int q = f >> 4; int c4 = f & 15;
        float4 v = *(const float4*)(QHp + (qrow0 + q) * 512 + h * 64 + c4 * 4);
        float va[4] = {v.x * SCALE_F, v.y * SCALE_F, v.z * SCALE_F, v.w * SCALE_F};
        #pragma unroll
        for (int i = 0; i < 4; i++) {
            int d = c4 * 4 + i;
            ((uint32_t*)Qs)[q * 64 + SWG(d >> 3, q) + KPERM(d & 7)] = f2tf(va[i]);
        }
    }

    float mr[2] = {NEG_INF_F, NEG_INF_F};
    float lr[2] = {0.f, 0.f};
    float O[8][4] = {};

    for (int t0 = 0; t0 < KP; t0 += 64) {
        __syncthreads();
        // ---- stage K (row=key, col=d swizzled KPERM; coalesced LDG) ----
        #pragma unroll
        for (int it = 0; it < 4; it++) {
            int f = tid + it * 256; int j = f >> 4; int c4 = f & 15;
            int jg = t0 + j;
            float4 kv = make_float4(0.f, 0.f, 0.f, 0.f);
            if (jg < KP)
                kv = *(const float4*)(KHp + ((size_t)b * KP + jg) * 512 + h * 64 + c4 * 4);
            float ka[4] = {kv.x, kv.y, kv.z, kv.w};
            #pragma unroll
            for (int i = 0; i < 4; i++) {
                int d = c4 * 4 + i;
                ((uint32_t*)Ks)[j * 64 + SWG(d >> 3, j) + KPERM(d & 7)] = f2tf(ka[i]);
            }
        }
        // ---- stage V transposed (row=d, col=key IDENTITY within group) ----
        #pragma unroll
        for (int it = 0; it < 4; it++) {
            int f = tid + it * 256; int j6 = f & 63; int dc = f >> 6;
            int jg = t0 + j6;
            float4 vv = make_float4(0.f, 0.f, 0.f, 0.f);
            if (jg < KP)
                vv = *(const float4*)(VHp + ((size_t)b * KP + jg) * 512 + h * 64 + dc * 4);
            float va[4] = {vv.x, vv.y, vv.z, vv.w};
            #pragma unroll
            for (int i = 0; i < 4; i++) {
                int d = dc * 4 + i;
                ((uint32_t*)Vs)[d * 64 + SWG(j6 >> 3, d) + (j6 & 7)] = f2tf(va[i]);
            }
        }
        if (tid < 64) {
            int jg = t0 + tid;
            bool valid = (jg < KLEN) ? (kmask[b * KLEN + jg] != 0) : (jg == KLEN);
            Ms[tid] = valid ? 0.0f : NEG_INF_F;
        }
        __syncthreads();

        // ---- S = Q K^T ----
        float s[8][4] = {};
        #pragma unroll
        for (int kg = 0; kg < 8; kg++) {
            uint2 a02 = *(uint2*)((uint32_t*)Qs + (qw + g) * 64 + SWG(kg, g) + 2 * t4);
            uint2 a13 = *(uint2*)((uint32_t*)Qs + (qw + g + 8) * 64 + SWG(kg, g) + 2 * t4);
            #pragma unroll
            for (int ni = 0; ni < 8; ni++) {
                uint2 bf = *(uint2*)((uint32_t*)Ks + (ni * 8 + g) * 64 + SWG(kg, g) + 2 * t4);
                mma8(s[ni], a02.x, a13.x, a02.y, a13.y, bf.x, bf.y);
            }
        }
        // mask
        #pragma unroll
        for (int ni = 0; ni < 8; ni++) {
            float2 mk = *(float2*)&Ms[ni * 8 + 2 * t4];
            s[ni][0] += mk.x; s[ni][1] += mk.y;
            s[ni][2] += mk.x; s[ni][3] += mk.y;
        }
        // ---- online softmax ----
        float mx0 = NEG_INF_F, mx1 = NEG_INF_F;
        #pragma unroll
        for (int ni = 0; ni < 8; ni++) {
            mx0 = fmaxf(mx0, fmaxf(s[ni][0], s[ni][1]));
            mx1 = fmaxf(mx1, fmaxf(s[ni][2], s[ni][3]));
        }
        mx0 = fmaxf(mx0, __shfl_xor_sync(0xffffffffu, mx0, 1));
        mx0 = fmaxf(mx0, __shfl_xor_sync(0xffffffffu, mx0, 2));
        mx1 = fmaxf(mx1, __shfl_xor_sync(0xffffffffu, mx1, 1));
        mx1 = fmaxf(mx1, __shfl_xor_sync(0xffffffffu, mx1, 2));
        float mn0 = fmaxf(mr[0], mx0), mn1 = fmaxf(mr[1], mx1);
        float al0 = __expf(mr[0] - mn0), al1 = __expf(mr[1] - mn1);
        float sum0 = 0.f, sum1 = 0.f;
        #pragma unroll
        for (int ni = 0; ni < 8; ni++) {
            s[ni][0] = __expf(s[ni][0] - mn0); sum0 += s[ni][0];
            s[ni][1] = __expf(s[ni][1] - mn0); sum0 += s[ni][1];
            s[ni][2] = __expf(s[ni][2] - mn1); sum1 += s[ni][2];
            s[ni][3] = __expf(s[ni][3] - mn1); sum1 += s[ni][3];
        }
        sum0 += __shfl_xor_sync(0xffffffffu, sum0, 1);
        sum0 += __shfl_xor_sync(0xffffffffu, sum0, 2);
        sum1 += __shfl_xor_sync(0xffffffffu, sum1, 1);
        sum1 += __shfl_xor_sync(0xffffffffu, sum1, 2);
        lr[0] = lr[0] * al0 + sum0;
        lr[1] = lr[1] * al1 + sum1;
        mr[0] = mn0; mr[1] = mn1;
        #pragma unroll
        for (int ni = 0; ni < 8; ni++) {
            O[ni][0] *= al0; O[ni][1] *= al0;
            O[ni][2] *= al1; O[ni][3] *= al1;
        }

        // ---- O += P V : A-fragment DIRECT from QK^T C-fragment registers ----
        // C frag: keys (kg*8+2t4, +2t4+1) for rows qw+g / qw+g+8.
        // A slots: t4 <- key 2t4 (s[kg][0]/s[kg][2]); t4+4 <- key 2t4+1 (s[kg][1]/s[kg][3]).
        // V identity placement puts key 2t4 -> B slot t4, key 2t4+1 -> slot t4+4: consistent.
        #pragma unroll
        for (int kg = 0; kg < 8; kg++) {
            uint32_t pa0 = f2tf(s[kg][0]);
            uint32_t pa1 = f2tf(s[kg][2]);
            uint32_t pa2 = f2tf(s[kg][1]);
            uint32_t pa3 = f2tf(s[kg][3]);
            #pragma unroll
            for (int ni = 0; ni < 8; ni++) {
                uint2 bf = *(uint2*)((uint32_t*)Vs + (ni * 8 + g) * 64 + SWG(kg, g) + 2 * t4);
                mma8(O[ni], pa0, pa1, pa2, pa3, bf.x, bf.y);
            }
        }
    }

    // ---- epilogue ----
    int r0 = qb + qw + g, r1 = r0 + 8;
    float qm0 = (qmask[b * QQ + r0] != 0) ? 1.0f : 0.0f;
    float qm1 = (qmask[b * QQ + r1] != 0) ? 1.0f : 0.0f;
    float inv0 = qm0 / lr[0], inv1 = qm1 / lr[1];
    #pragma unroll
    for (int ni = 0; ni < 8; ni++) {
        int c = h * 64 + ni * 8 + 2 * t4;
        *(float2*)(AV + (qrow0 + qw + g) * 512 + c) =
            make_float2(O[ni][0] * inv0, O[ni][1] * inv0);
        *(float2*)(AV + (qrow0 + qw + g + 8) * 512 + c) =
            make_float2(O[ni][2] * inv1, O[ni][3] * inv1);
    }
}

// ---------------- launch ------------------------------------------------------
extern "C" void kernel_launch(void* const* d_in, const int* in_sizes, int n_in,
                              void* d_out, int out_size) {
    const float* query = (const float*)d_in[0];
    const float* key   = (const float*)d_in[1];
    const float* value = (const float*)d_in[2];
    const float* wq    = (const float*)d_in[3];
    const float* wk    = (const float*)d_in[4];
    const float* wv    = (const float*)d_in[5];
    const float* wo    = (const float*)d_in[6];
    const float* gw    = (const float*)d_in[7];
    const float* gb    = (const float*)d_in[8];
    const float* qg    = (const float*)d_in[9];
    const float* qbv   = (const float*)d_in[10];
    const float* kg    = (const float*)d_in[11];
    const float* kbv   = (const float*)d_in[12];
    const float* vg    = (const float*)d_in[13];
    const float* vbv   = (const float*)d_in[14];
    const int* qmask   = (const int*)d_in[15];
    const int* kmask   = (const int*)d_in[16];
    float* out = (float*)d_out;

    float *QN, *KN, *VN, *QH, *KH, *VH, *AV, *AVO;
    float *Pq, *Pk, *Pv, *Po, *Pg;
    cudaGetSymbolAddress((void**)&QN,  g_QN);
    cudaGetSymbolAddress((void**)&KN,  g_KN);
    cudaGetSymbolAddress((void**)&VN,  g_VN);
    cudaGetSymbolAddress((void**)&QH,  g_QH);
    cudaGetSymbolAddress((void**)&KH,  g_KH);
    cudaGetSymbolAddress((void**)&VH,  g_VH);
    cudaGetSymbolAddress((void**)&AV,  g_AV);
    cudaGetSymbolAddress((void**)&AVO, g_AVO);
    cudaGetSymbolAddress((void**)&Pq,  g_Pq);
    cudaGetSymbolAddress((void**)&Pk,  g_Pk);
    cudaGetSymbolAddress((void**)&Pv,  g_Pv);
    cudaGetSymbolAddress((void**)&Po,  g_Po);
    cudaGetSymbolAddress((void**)&Pg,  g_Pg);

    cudaFuncSetAttribute(attn_kernel, cudaFuncAttributeMaxDynamicSharedMemorySize, ATT_SMEM);
    cudaFuncSetAttribute(mm_qkv, cudaFuncAttributeMaxDynamicSharedMemorySize, GEMM_SMEM);
    cudaFuncSetAttribute(mm_single, cudaFuncAttributeMaxDynamicSharedMemorySize, GEMM_SMEM);
    cudaFuncSetAttribute(mm_gnet, cudaFuncAttributeMaxDynamicSharedMemorySize, GEMM_SMEM);

    // 0) weight prep (transpose + fragment-permute + tf32 convert), one launch
    prep_w<<<dim3(32, 16, 5), dim3(32, 8)>>>(wq, wk, wv, wo, gw, Pq, Pk, Pv, Po, Pg);

    // 1) pre-layernorm (merged)
    ln3_kernel<<<dim3(BB * KP, 3), 128>>>(query, key, value, qg, qbv, kg, kbv,
                                          vg, vbv, QN, KN, VN);

    // 2) projections (merged QKV, tf32 warp MMA, prepped weights)
    mm_qkv<<<dim3(4, 65, 3), 256, GEMM_SMEM>>>(QN, KN, VN, Pq, Pk, Pv, QH, KH, VH);

    // 3) flash attention (register-direct PV)
    attn_kernel<<<dim3(QQ / 128, NH, BB), 256, ATT_SMEM>>>(QH, KH, VH, kmask, qmask, AV);

    // 4) output projection
    mm_single<<<dim3(4, 64), 256, GEMM_SMEM>>>(AV, Po, AVO, BB * QQ);

    // 5) g_net + gate + residual
    mm_gnet<<<dim3(4, 64), 256, GEMM_SMEM>>>(query, AVO, Pg, gb, out);
}

// round 14
// speedup vs baseline: 1.7116x; 1.0007x over previous
#include <cuda_runtime.h>
#include <math.h>
#include <stdint.h>

#define BB   2
#define QQ   2048
#define KLEN 2048
#define KP   2049
#define DD   512
#define NH   8
#define HD   64
#define SCALE_F   0.125f
#define NEG_INF_F -1e30f
#define LN_EPS_F  1e-5f

// ---------------- tf32 mma helpers -------------------------------------------
__device__ __forceinline__ uint32_t f2tf(float f) {
    uint32_t u; asm("cvt.rna.tf32.f32 %0, %1;" : "=r"(u) : "f"(f)); return u;
}
__device__ __forceinline__ void mma8(float c[4], uint32_t a0, uint32_t a1,
                                     uint32_t a2, uint32_t a3,
                                     uint32_t b0, uint32_t b1) {
    asm volatile("mma.sync.aligned.m16n8k8.row.col.f32.tf32.tf32.f32 "
        "{%0,%1,%2,%3}, {%4,%5,%6,%7}, {%8,%9}, {%0,%1,%2,%3};"
        : "+f"(c[0]), "+f"(c[1]), "+f"(c[2]), "+f"(c[3])
        : "r"(a0), "r"(a1), "r"(a2), "r"(a3), "r"(b0), "r"(b1));
}

// fragment k-permutation within a k8 group: p = ((kk&3)<<1)|(kk>>2)
#define KPERM(kk) ((((kk) & 3) << 1) | ((kk) >> 2))
// XOR swizzle of k-group by row (rows stride multiple of 32 words)
#define SWG(kg, r) ((((kg) ^ ((r) & 3)) << 3))

// ---------------- scratch ----------------------------------------------------
__device__ float g_QN[BB * QQ * DD];
__device__ float g_KN[BB * KP * DD];
__device__ float g_VN[BB * KP * DD];
__device__ float g_QH[BB * QQ * DD];
__device__ float g_KH[BB * KP * DD];
__device__ float g_VH[BB * KP * DD];
__device__ float g_AV[BB * QQ * DD];
__device__ float g_AVO[BB * QQ * DD];
// prepped weights: tf32 bits, layout [(kt*512 + n)*32 + (kg*8 + KPERM(kk))]
__device__ float g_Pq[DD * DD];
__device__ float g_Pk[DD * DD];
__device__ float g_Pv[DD * DD];
__device__ float g_Po[DD * DD];
__device__ float g_Pg[2 * DD * DD];

// ---------------- weight prep: transpose + permute + tf32-convert -------------
__global__ void prep_w(const float* __restrict__ wq, const float* __restrict__ wk,
                       const float* __restrict__ wv, const float* __restrict__ wo,
                       const float* __restrict__ gw,
                       float* __restrict__ Pq, float* __restrict__ Pk,
                       float* __restrict__ Pv, float* __restrict__ Po,
                       float* __restrict__ Pg) {
    int z = blockIdx.z;
    const float* W = (z == 0) ? wq : (z == 1) ? wk : (z == 2) ? wv
                   : (z == 3) ? wo : gw;
    float* P       = (z == 0) ? Pq : (z == 1) ? Pk : (z == 2) ? Pv
                   : (z == 3) ? Po : Pg;
    int K = (z == 4) ? 1024 : 512;
    int kt = blockIdx.x;
    if (kt * 32 >= K) return;
    int n0 = blockIdx.y * 32;

    __shared__ float t[32][33];
    int x = threadIdx.x, y = threadIdx.y;   // block (32, 8)
    #pragma unroll
    for (int i = 0; i < 4; i++)
        t[y + 8 * i][x] = W[(size_t)(kt * 32 + y + 8 * i) * 512 + n0 + x];
    __syncthreads();

    int kg = x >> 3, p = x & 7;
    int kk = ((p & 1) << 2) | (p >> 1);     // inverse of KPERM
    int krow = kg * 8 + kk;
    #pragma unroll
    for (int i = 0; i < 4; i++) {
        int nn = y + 8 * i;
        P[((size_t)(kt * 512) + n0 + nn) * 32 + x] =
            __uint_as_float(f2tf(t[krow][nn]));
    }
}

// ---------------- merged LayerNorm (y selects q/k/v) --------------------------
__global__ void ln3_kernel(const float* __restrict__ xq,
                           const float* __restrict__ xk,
                           const float* __restrict__ xv,
                           const float* __restrict__ qg, const float* __restrict__ qb,
                           const float* __restrict__ kg, const float* __restrict__ kb,
                           const float* __restrict__ vg, const float* __restrict__ vb,
                           float* __restrict__ yq, float* __restrict__ yk,
                           float* __restrict__ yv) {
    int z = blockIdx.y;
    const float* x     = (z == 0) ? xq : (z == 1) ? xk : xv;
    const float* gamma = (z == 0) ? qg : (z == 1) ? kg : vg;
    const float* beta  = (z == 0) ? qb : (z == 1) ? kb : vb;
    float* y           = (z == 0) ? yq : (z == 1) ? yk : yv;
    int rows_in  = (z == 0) ? QQ : KLEN;
    int rows_out = (z == 0) ? QQ : KP;

    int r = blockIdx.x;
    if (r >= BB * rows_out) return;
    int b = r / rows_out;
    int j = r - b * rows_out;
    int t = threadIdx.x;

    float4 g4 = ((const float4*)gamma)[t];
    float4 b4 = ((const float4*)beta)[t];
    float4* yr = (float4*)(y + (size_t)r * DD);

    if (j >= rows_in) { yr[t] = b4; return; }

    const float4* xr = (const float4*)(x + ((size_t)b * rows_in + j) * DD);
    float4 v = xr[t];
    float s  = v.x + v.y + v.z + v.w;
    float sq = v.x*v.x + v.y*v.y + v.z*v.z + v.w*v.w;
    #pragma unroll
    for (int o = 16; o > 0; o >>= 1) {
        s  += __shfl_xor_sync(0xffffffffu, s,  o);
        sq += __shfl_xor_sync(0xffffffffu, sq, o);
    }
    __shared__ float rs[4], rq[4];
    int w = t >> 5;
    if ((t & 31) == 0) { rs[w] = s; rq[w] = sq; }
    __syncthreads();
    s  = rs[0] + rs[1] + rs[2] + rs[3];
    sq = rq[0] + rq[1] + rq[2] + rq[3];

    float mean = s * (1.0f / DD);
    float var  = sq * (1.0f / DD) - mean * mean;
    float rstd = rsqrtf(var + LN_EPS_F);

    float4 o;
    o.x = (v.x - mean) * rstd * g4.x + b4.x;
    o.y = (v.y - mean) * rstd * g4.y + b4.y;
    o.z = (v.z - mean) * rstd * g4.z + b4.z;
    o.w = (v.w - mean) * rstd * g4.w + b4.w;
    yr[t] = o;
}

// ---------------- tf32 warp-MMA GEMM body -------------------------------------
// BM=64, BN=128, BK=32; 256 thr = 8 warps (2m x 4n), warp tile 32x32.
// XOR-swizzled smem (stride 32 words): conflict-free fragment LDS.64.
#define GEMM_SMEM ((2 * 64 * 32 + 2 * 128 * 32) * 4)

extern __shared__ float smf[];

__device__ __forceinline__ void gemm_body(const float* __restrict__ A,
                                          const float* __restrict__ P,
                                          float* __restrict__ C, int M,
                                          int n0, int m0) {
    float* As0 = smf;
    float* As1 = smf + 64 * 32;
    float* Bs0 = smf + 2 * 64 * 32;
    float* Bs1 = smf + 2 * 64 * 32 + 128 * 32;
    int tid = threadIdx.x;
    int lane = tid & 31, wid = tid >> 5;
    int g = lane >> 2, t4 = lane & 3;
    int mw = wid & 1, nw = wid >> 1;

    float acc[2][4][4] = {};
    float4 ra[2], rb[4];

    auto ldg = [&](int kt) {
        int k0 = kt * 32;
        #pragma unroll
        for (int it = 0; it < 2; it++) {
            int f = tid + it * 256;            // 0..511
            int r = f >> 3; int c4 = f & 7;
            int gm = m0 + r; if (gm > M - 1) gm = M - 1;
            ra[it] = *(const float4*)(A + (size_t)gm * 512 + k0 + c4 * 4);
        }
        const float* Pb = P + ((size_t)kt * 512 + n0) * 32;
        #pragma unroll
        for (int it = 0; it < 4; it++) {
            int f = tid + it * 256;            // 0..1023
            int nr = f >> 3; int c4 = f & 7;
            rb[it] = *(const float4*)(Pb + (size_t)nr * 32 + c4 * 4);
        }
    };
    auto sts = [&](float* Ab, float* Bb) {
        #pragma unroll
        for (int it = 0; it < 2; it++) {
            int f = tid + it * 256;
            int r = f >> 3; int c4 = f & 7;
            float va[4] = {ra[it].x, ra[it].y, ra[it].z, ra[it].w};
            #pragma unroll
            for (int i = 0; i < 4; i++) {
                int k = c4 * 4 + i;
                ((uint32_t*)Ab)[r * 32 + SWG(k >> 3, r) + KPERM(k & 7)] = f2tf(va[i]);
            }
        }
        #pragma unroll
        for (int it = 0; it < 4; it++) {
            int f = tid + it * 256;
            int nr = f >> 3; int c4 = f & 7;
            *(float4*)&Bb[nr * 32 + SWG(c4 >> 1, nr) + (c4 & 1) * 4] = rb[it];
        }
    };
    auto compute = [&](float* Ab, float* Bb) {
        #pragma unroll
        for (int kg = 0; kg < 4; kg++) {
            uint2 a02[2], a13[2];
            #pragma unroll
            for (int mi = 0; mi < 2; mi++) {
                int r = mw * 32 + mi * 16 + g;
                a02[mi] = *(uint2*)((uint32_t*)Ab + r * 32 + SWG(kg, g) + 2 * t4);
                a13[mi] = *(uint2*)((uint32_t*)Ab + (r + 8) * 32 + SWG(kg, g) + 2 * t4);
            }
            #pragma unroll
            for (int ni = 0; ni < 4; ni++) {
                int nr = nw * 32 + ni * 8 + g;
                uint2 bf = *(uint2*)((uint32_t*)Bb + nr * 32 + SWG(kg, g) + 2 * t4);
                #pragma unroll
                for (int mi = 0; mi < 2; mi++)
                    mma8(acc[mi][ni], a02[mi].x, a13[mi].x, a02[mi].y, a13[mi].y,
                         bf.x, bf.y);
            }
        }
    };

    ldg(0); sts(As0, Bs0); __syncthreads();
    const int T = 16;
    for (int t = 0; t < T; t++) {
        if (t + 1 < T) ldg(t + 1);
        if (t & 1) compute(As1, Bs1); else compute(As0, Bs0);
        if (t + 1 < T) { if (t & 1) sts(As0, Bs0); else sts(As1, Bs1); }
        __syncthreads();
    }

    #pragma unroll
    for (int mi = 0; mi < 2; mi++) {
        int r0 = m0 + mw * 32 + mi * 16 + g;
        #pragma unroll
        for (int ni = 0; ni < 4; ni++) {
            int c = n0 + nw * 32 + ni * 8 + 2 * t4;
            if (r0 < M)
                *(float2*)(C + (size_t)r0 * 512 + c) =
                    make_float2(acc[mi][ni][0], acc[mi][ni][1]);
            if (r0 + 8 < M)
                *(float2*)(C + (size_t)(r0 + 8) * 512 + c) =
                    make_float2(acc[mi][ni][2], acc[mi][ni][3]);
        }
    }
}

// merged QKV projection: blockIdx.z selects which projection
__global__ void __launch_bounds__(256, 2) mm_qkv(const float* __restrict__ QN,
                                                 const float* __restrict__ KN,
                                                 const float* __restrict__ VN,
                                                 const float* __restrict__ Pq,
                                                 const float* __restrict__ Pk,
                                                 const float* __restrict__ Pv,
                                                 float* __restrict__ QH,
                                                 float* __restrict__ KH,
                                                 float* __restrict__ VH) {
    int z = blockIdx.z;
    const float* A = (z == 0) ? QN : (z == 1) ? KN : VN;
    const float* P = (z == 0) ? Pq : (z == 1) ? Pk : Pv;
    float* C       = (z == 0) ? QH : (z == 1) ? KH : VH;
    int M = (z == 0) ? BB * QQ : BB * KP;
    int m0 = blockIdx.y * 64;
    if (m0 >= M) return;
    gemm_body(A, P, C, M, blockIdx.x * 128, m0);
}

__global__ void __launch_bounds__(256, 2) mm_single(const float* __restrict__ A,
                                                    const float* __restrict__ P,
                                                    float* __restrict__ C, int M) {
    gemm_body(A, P, C, M, blockIdx.x * 128, blockIdx.y * 64);
}

// ---------------- g_net GEMM (K=1024, prepped weights) + gated residual -------
__global__ void __launch_bounds__(256, 2) mm_gnet(const float* __restrict__ Aq,
                                                  const float* __restrict__ Av,
                                                  const float* __restrict__ Pg,
                                                  const float* __restrict__ gbv,
                                                  float* __restrict__ out) {
    float* As0 = smf;
    float* As1 = smf + 64 * 32;
    float* Bs0 = smf + 2 * 64 * 32;
    float* Bs1 = smf + 2 * 64 * 32 + 128 * 32;
    int tid = threadIdx.x;
    int lane = tid & 31, wid = tid >> 5;
    int g = lane >> 2, t4 = lane & 3;
    int mw = wid & 1, nw = wid >> 1;
    int n0 = blockIdx.x * 128, m0 = blockIdx.y * 64;

    float acc[2][4][4] = {};
    float4 ra[2], rb[4];

    auto ldg = [&](int kt) {
        const float* Ap = (kt < 16) ? Aq : Av;
        int ka = (kt & 15) * 32;
        #pragma unroll
        for (int it = 0; it < 2; it++) {
            int f = tid + it * 256;
            int r = f >> 3; int c4 = f & 7;
            ra[it] = *(const float4*)(Ap + (size_t)(m0 + r) * 512 + ka + c4 * 4);
        }
        const float* Pb = Pg + ((size_t)kt * 512 + n0) * 32;
        #pragma unroll
        for (int it = 0; it < 4; it++) {
            int f = tid + it * 256;
            int nr = f >> 3; int c4 = f & 7;
            rb[it] = *(const float4*)(Pb + (size_t)nr * 32 + c4 * 4);
        }
    };
    auto sts = [&](float* Ab, float* Bb) {
        #pragma unroll
        for (int it = 0; it < 2; it++) {
            int f = tid + it * 256;
            int r = f >> 3; int c4 = f & 7;
            float va[4] = {ra[it].x, ra[it].y, ra[it].z, ra[it].w};
            #pragma unroll
            for (int i = 0; i < 4; i++) {
                int k = c4 * 4 + i;
                ((uint32_t*)Ab)[r * 32 + SWG(k >> 3, r) + KPERM(k & 7)] = f2tf(va[i]);
            }
        }
        #pragma unroll
        for (int it = 0; it < 4; it++) {
            int f = tid + it * 256;
            int nr = f >> 3; int c4 = f & 7;
            *(float4*)&Bb[nr * 32 + SWG(c4 >> 1, nr) + (c4 & 1) * 4] = rb[it];
        }
    };
    auto compute = [&](float* Ab, float* Bb) {
        #pragma unroll
        for (int kg = 0; kg < 4; kg++) {
            uint2 a02[2], a13[2];
            #pragma unroll
            for (int mi = 0; mi < 2; mi++) {
                int r = mw * 32 + mi * 16 + g;
                a02[mi] = *(uint2*)((uint32_t*)Ab + r * 32 + SWG(kg, g) + 2 * t4);
                a13[mi] = *(uint2*)((uint32_t*)Ab + (r + 8) * 32 + SWG(kg, g) + 2 * t4);
            }
            #pragma unroll
            for (int ni = 0; ni < 4; ni++) {
                int nr = nw * 32 + ni * 8 + g;
                uint2 bf = *(uint2*)((uint32_t*)Bb + nr * 32 + SWG(kg, g) + 2 * t4);
                #pragma unroll
                for (int mi = 0; mi < 2; mi++)
                    mma8(acc[mi][ni], a02[mi].x, a13[mi].x, a02[mi].y, a13[mi].y,
                         bf.x, bf.y);
            }
        }
    };

    ldg(0); sts(As0, Bs0); __syncthreads();
    const int T = 32;
    for (int t = 0; t < T; t++) {
        if (t + 1 < T) ldg(t + 1);
        if (t & 1) compute(As1, Bs1); else compute(As0, Bs0);
        if (t + 1 < T) { if (t & 1) sts(As0, Bs0); else sts(As1, Bs1); }
        __syncthreads();
    }

    #pragma unroll
    for (int mi = 0; mi < 2; mi++) {
        int r0 = m0 + mw * 32 + mi * 16 + g;
        #pragma unroll
        for (int ni = 0; ni < 4; ni++) {
            int c = n0 + nw * 32 + ni * 8 + 2 * t4;
            float2 bb = *(const float2*)(gbv + c);
            #pragma unroll
            for (int sel = 0; sel < 2; sel++) {
                size_t r = r0 + sel * 8;
                float2 qv = *(const float2*)(Aq + r * 512 + c);
                float2 av = *(const float2*)(Av + r * 512 + c);
                float s0 = acc[mi][ni][sel * 2 + 0] + bb.x;
                float s1 = acc[mi][ni][sel * 2 + 1] + bb.y;
                float g0 = 1.0f / (1.0f + __expf(-s0));
                float g1 = 1.0f / (1.0f + __expf(-s1));
                float o0 = qv.x + g0 * qv.x + (1.0f - g0) * av.x;
                float o1 = qv.y + g1 * qv.y + (1.0f - g1) * av.y;
                *(float2*)(out + r * 512 + c) = make_float2(o0, o1);
            }
        }
    }
}

// ---------------- flash attention: register-direct PV (no P SMEM round-trip) --
// Buffers stride 64 words: Qs[128] Ks[64] Vs[64] + Ms[64]. 65.8KB -> 2 CTA/SM.
// PV mma A-fragment comes straight from the QK^T C-fragment registers; V uses
// IDENTITY within-group key placement so both operands agree on k-order.
#define ATT_SMEM (((128 + 64 + 64) * 64 + 64) * 4)

__global__ void __launch_bounds__(256, 2) attn_kernel(const float* __restrict__ QHp,
                                                      const float* __restrict__ KHp,
                                                      const float* __restrict__ VHp,
                                                      const int* __restrict__ kmask,
                                                      const int* __restrict__ qmask,
                                                      float* __restrict__ AV) {
    float* Qs = smf;                 // [128][64] tf32, swizzled (KPERM over d)
    float* Ks = Qs + 128 * 64;       // [64][64]  rows=keys, cols=d (KPERM)
    float* Vs = Ks + 64 * 64;        // [64][64]  rows=d,    cols=keys (identity)
    float* Ms = Vs + 64 * 64;        // [64]

    int tid = threadIdx.x;
    int lane = tid & 31, wid = tid >> 5;
    int g = lane >> 2, t4 = lane & 3;
    int qw = wid * 16;
    int qb = blockIdx.x * 128, h = blockIdx.y, b = blockIdx.z;
    size_t qrow0 = (size_t)b * QQ + qb;

    // stage Q (pre-scaled, tf32, swizzled, KPERM over d)
    #pragma unroll
    for (int it = 0; it < 8; it++) {
        int f = tid + it * 256; int q = f >> 4; int c4 = f & 15;
        float4 v = *(const float4*)(QHp + (qrow0 + q) * 512 + h * 64 + c4 * 4);
        float va[4] = {v.x * SCALE_F, v.y * SCALE_F, v.z * SCALE_F, v.w * SCALE_F};
        #pragma unroll
        for (int i = 0; i < 4; i++) {
            int d = c4 * 4 + i;
            ((uint32_t*)Qs)[q * 64 + SWG(d >> 3, q) + KPERM(d & 7)] = f2tf(va[i]);
        }
    }

    float mr[2] = {NEG_INF_F, NEG_INF_F};
    float lr[2] = {0.f, 0.f};
    float O[8][4] = {};

    for (int t0 = 0; t0 < KP; t0 += 64) {
        __syncthreads();
        // ---- stage K (row=key, col=d swizzled KPERM; coalesced LDG) ----
        #pragma unroll
        for (int it = 0; it < 4; it++) {
            int f = tid + it * 256; int j = f >> 4; int c4 = f & 15;
            int jg = t0 + j;
            float4 kv = make_float4(0.f, 0.f, 0.f, 0.f);
            if (jg < KP)
                kv = *(const float4*)(KHp + ((size_t)b * KP + jg) * 512 + h * 64 + c4 * 4);
            float ka[4] = {kv.x, kv.y, kv.z, kv.w};
            #pragma unroll
            for (int i = 0; i < 4; i++) {
                int d = c4 * 4 + i;
                ((uint32_t*)Ks)[j * 64 + SWG(d >> 3, j) + KPERM(d & 7)] = f2tf(ka[i]);
            }
        }
        // ---- stage V transposed (row=d, col=key IDENTITY within group) ----
        #pragma unroll
        for (int it = 0; it < 4; it++) {
            int f = tid + it * 256; int j6 = f & 63; int dc = f >> 6;
            int jg = t0 + j6;
            float4 vv = make_float4(0.f, 0.f, 0.f, 0.f);
            if (jg < KP)
                vv = *(const float4*)(VHp + ((size_t)b * KP + jg) * 512 + h * 64 + dc * 4);
            float va[4] = {vv.x, vv.y, vv.z, vv.w};
            #pragma unroll
            for (int i = 0; i < 4; i++) {
                int d = dc * 4 + i;
                ((uint32_t*)Vs)[d * 64 + SWG(j6 >> 3, d) + (j6 & 7)] = f2tf(va[i]);
            }
        }
        if (tid < 64) {
            int jg = t0 + tid;
            bool valid = (jg < KLEN) ? (kmask[b * KLEN + jg] != 0) : (jg == KLEN);
            Ms[tid] = valid ? 0.0f : NEG_INF_F;
        }
        __syncthreads();

        // ---- S = Q K^T ----
        float s[8][4] = {};
        #pragma unroll
        for (int kg = 0; kg < 8; kg++) {
            uint2 a02 = *(uint2*)((uint32_t*)Qs + (qw + g) * 64 + SWG(kg, g) + 2 * t4);
            uint2 a13 = *(uint2*)((uint32_t*)Qs + (qw + g + 8) * 64 + SWG(kg, g) + 2 * t4);
            #pragma unroll
            for (int ni = 0; ni < 8; ni++) {
                uint2 bf = *(uint2*)((uint32_t*)Ks + (ni * 8 + g) * 64 + SWG(kg, g) + 2 * t4);
                mma8(s[ni], a02.x, a13.x, a02.y, a13.y, bf.x, bf.y);
            }
        }
        // mask
        #pragma unroll
        for (int ni = 0; ni < 8; ni++) {
            float2 mk = *(float2*)&Ms[ni * 8 + 2 * t4];
            s[ni][0] += mk.x; s[ni][1] += mk.y;
            s[ni][2] += mk.x; s[ni][3] += mk.y;
        }
        // ---- online softmax ----
        float mx0 = NEG_INF_F, mx1 = NEG_INF_F;
        #pragma unroll
        for (int ni = 0; ni < 8; ni++) {
            mx0 = fmaxf(mx0, fmaxf(s[ni][0], s[ni][1]));
            mx1 = fmaxf(mx1, fmaxf(s[ni][2], s[ni][3]));
        }
        mx0 = fmaxf(mx0, __shfl_xor_sync(0xffffffffu, mx0, 1));
        mx0 = fmaxf(mx0, __shfl_xor_sync(0xffffffffu, mx0, 2));
        mx1 = fmaxf(mx1, __shfl_xor_sync(0xffffffffu, mx1, 1));
        mx1 = fmaxf(mx1, __shfl_xor_sync(0xffffffffu, mx1, 2));
        float mn0 = fmaxf(mr[0], mx0), mn1 = fmaxf(mr[1], mx1);
        float al0 = __expf(mr[0] - mn0), al1 = __expf(mr[1] - mn1);
        float sum0 = 0.f, sum1 = 0.f;
        #pragma unroll
        for (int ni = 0; ni < 8; ni++) {
            s[ni][0] = __expf(s[ni][0] - mn0); sum0 += s[ni][0];
            s[ni][1] = __expf(s[ni][1] - mn0); sum0 += s[ni][1];
            s[ni][2] = __expf(s[ni][2] - mn1); sum1 += s[ni][2];
            s[ni][3] = __expf(s[ni][3] - mn1); sum1 += s[ni][3];
        }
        sum0 += __shfl_xor_sync(0xffffffffu, sum0, 1);
        sum0 += __shfl_xor_sync(0xffffffffu, sum0, 2);
        sum1 += __shfl_xor_sync(0xffffffffu, sum1, 1);
        sum1 += __shfl_xor_sync(0xffffffffu, sum1, 2);
        lr[0] = lr[0] * al0 + sum0;
        lr[1] = lr[1] * al1 + sum1;
        mr[0] = mn0; mr[1] = mn1;
        #pragma unroll
        for (int ni = 0; ni < 8; ni++) {
            O[ni][0] *= al0; O[ni][1] *= al0;
            O[ni][2] *= al1; O[ni][3] *= al1;
        }

        // ---- O += P V : A-fragment DIRECT from QK^T C-fragment registers ----
        // C frag: keys (kg*8+2t4, +2t4+1) for rows qw+g / qw+g+8.
        // A slots: t4 <- key 2t4 (s[kg][0]/s[kg][2]); t4+4 <- key 2t4+1 (s[kg][1]/s[kg][3]).
        // V identity placement puts key 2t4 -> B slot t4, key 2t4+1 -> slot t4+4: consistent.
        #pragma unroll
        for (int kg = 0; kg < 8; kg++) {
            uint32_t pa0 = f2tf(s[kg][0]);
            uint32_t pa1 = f2tf(s[kg][2]);
            uint32_t pa2 = f2tf(s[kg][1]);
            uint32_t pa3 = f2tf(s[kg][3]);
            #pragma unroll
            for (int ni = 0; ni < 8; ni++) {
                uint2 bf = *(uint2*)((uint32_t*)Vs + (ni * 8 + g) * 64 + SWG(kg, g) + 2 * t4);
                mma8(O[ni], pa0, pa1, pa2, pa3, bf.x, bf.y);
            }
        }
    }

    // ---- epilogue ----
    int r0 = qb + qw + g, r1 = r0 + 8;
    float qm0 = (qmask[b * QQ + r0] != 0) ? 1.0f : 0.0f;
    float qm1 = (qmask[b * QQ + r1] != 0) ? 1.0f : 0.0f;
    float inv0 = qm0 / lr[0], inv1 = qm1 / lr[1];
    #pragma unroll
    for (int ni = 0; ni < 8; ni++) {
        int c = h * 64 + ni * 8 + 2 * t4;
        *(float2*)(AV + (qrow0 + qw + g) * 512 + c) =
            make_float2(O[ni][0] * inv0, O[ni][1] * inv0);
        *(float2*)(AV + (qrow0 + qw + g + 8) * 512 + c) =
            make_float2(O[ni][2] * inv1, O[ni][3] * inv1);
    }
}

// ---------------- launch ------------------------------------------------------
extern "C" void kernel_launch(void* const* d_in, const int* in_sizes, int n_in,
                              void* d_out, int out_size) {
    const float* query = (const float*)d_in[0];
    const float* key   = (const float*)d_in[1];
    const float* value = (const float*)d_in[2];
    const float* wq    = (const float*)d_in[3];
    const float* wk    = (const float*)d_in[4];
    const float* wv    = (const float*)d_in[5];
    const float* wo    = (const float*)d_in[6];
    const float* gw    = (const float*)d_in[7];
    const float* gb    = (const float*)d_in[8];
    const float* qg    = (const float*)d_in[9];
    const float* qbv   = (const float*)d_in[10];
    const float* kg    = (const float*)d_in[11];
    const float* kbv   = (const float*)d_in[12];
    const float* vg    = (const float*)d_in[13];
    const float* vbv   = (const float*)d_in[14];
    const int* qmask   = (const int*)d_in[15];
    const int* kmask   = (const int*)d_in[16];
    float* out = (float*)d_out;

    float *QN, *KN, *VN, *QH, *KH, *VH, *AV, *AVO;
    float *Pq, *Pk, *Pv, *Po, *Pg;
    cudaGetSymbolAddress((void**)&QN,  g_QN);
    cudaGetSymbolAddress((void**)&KN,  g_KN);
    cudaGetSymbolAddress((void**)&VN,  g_VN);
    cudaGetSymbolAddress((void**)&QH,  g_QH);
    cudaGetSymbolAddress((void**)&KH,  g_KH);
    cudaGetSymbolAddress((void**)&VH,  g_VH);
    cudaGetSymbolAddress((void**)&AV,  g_AV);
    cudaGetSymbolAddress((void**)&AVO, g_AVO);
    cudaGetSymbolAddress((void**)&Pq,  g_Pq);
    cudaGetSymbolAddress((void**)&Pk,  g_Pk);
    cudaGetSymbolAddress((void**)&Pv,  g_Pv);
    cudaGetSymbolAddress((void**)&Po,  g_Po);
    cudaGetSymbolAddress((void**)&Pg,  g_Pg);

    cudaFuncSetAttribute(attn_kernel, cudaFuncAttributeMaxDynamicSharedMemorySize, ATT_SMEM);
    cudaFuncSetAttribute(mm_qkv, cudaFuncAttributeMaxDynamicSharedMemorySize, GEMM_SMEM);
    cudaFuncSetAttribute(mm_single, cudaFuncAttributeMaxDynamicSharedMemorySize, GEMM_SMEM);
    cudaFuncSetAttribute(mm_gnet, cudaFuncAttributeMaxDynamicSharedMemorySize, GEMM_SMEM);

    // 0) weight prep (transpose + fragment-permute + tf32 convert), one launch
    prep_w<<<dim3(32, 16, 5), dim3(32, 8)>>>(wq, wk, wv, wo, gw, Pq, Pk, Pv, Po, Pg);

    // 1) pre-layernorm (merged)
    ln3_kernel<<<dim3(BB * KP, 3), 128>>>(query, key, value, qg, qbv, kg, kbv,
                                          vg, vbv, QN, KN, VN);

    // 2) projections (merged QKV, tf32 warp MMA, prepped weights)
    mm_qkv<<<dim3(4, 65, 3), 256, GEMM_SMEM>>>(QN, KN, VN, Pq, Pk, Pv, QH, KH, VH);

    // 3) flash attention (register-direct PV)
    attn_kernel<<<dim3(QQ / 128, NH, BB), 256, ATT_SMEM>>>(QH, KH, VH, kmask, qmask, AV);

    // 4) output projection
    mm_single<<<dim3(4, 64), 256, GEMM_SMEM>>>(AV, Po, AVO, BB * QQ);

    // 5) g_net + gate + residual
    mm_gnet<<<dim3(4, 64), 256, GEMM_SMEM>>>(query, AVO, Pg, gb, out);
}